// round 6
// baseline (speedup 1.0000x reference)
#include <cuda_runtime.h>
#include <cuda_bf16.h>
#include <cstdint>

#define B_SZ    2
#define S_LEN   2048
#define D_MODEL 1024
#define N_HEADS 16
#define HD      64
#define M_TOT   (B_SZ * S_LEN)   // 4096

typedef __nv_bfloat16 bf16;
typedef __nv_bfloat162 bf162;

// ---------------- scratch (device globals; no allocation allowed) ----------
__device__ bf16 g_xhi[M_TOT * D_MODEL];               // hidden split
__device__ bf16 g_xlo[M_TOT * D_MODEL];
__device__ bf16 g_wahi[3 * D_MODEL * D_MODEL];        // w_attn^T split [3072][1024]
__device__ bf16 g_walo[3 * D_MODEL * D_MODEL];
__device__ bf16 g_wphi[D_MODEL * D_MODEL];            // w_proj^T split [1024][1024]
__device__ bf16 g_wplo[D_MODEL * D_MODEL];
__device__ bf16 g_chi[M_TOT * D_MODEL];               // ctx split (written by attn)
__device__ bf16 g_clo[M_TOT * D_MODEL];

// attention operands, split bf16, layout [B,H,S,hd]
__device__ bf16 g_qhi[B_SZ * N_HEADS * S_LEN * HD];   // pre-scaled by 0.125
__device__ bf16 g_qlo[B_SZ * N_HEADS * S_LEN * HD];
__device__ bf16 g_khi[B_SZ * N_HEADS * S_LEN * HD];
__device__ bf16 g_klo[B_SZ * N_HEADS * S_LEN * HD];
__device__ bf16 g_vhi[B_SZ * N_HEADS * S_LEN * HD];
__device__ bf16 g_vlo[B_SZ * N_HEADS * S_LEN * HD];

// ======================= helpers ===========================================
__device__ __forceinline__ uint32_t smem_u32(const void* p) {
    uint32_t a;
    asm("{ .reg .u64 t; cvta.to.shared.u64 t, %1; cvt.u32.u64 %0, t; }" : "=r"(a) : "l"(p));
    return a;
}
__device__ __forceinline__ void ldsm_x4(uint32_t (&r)[4], uint32_t addr) {
    asm volatile("ldmatrix.sync.aligned.m8n8.x4.shared.b16 {%0,%1,%2,%3}, [%4];"
        : "=r"(r[0]), "=r"(r[1]), "=r"(r[2]), "=r"(r[3]) : "r"(addr));
}
__device__ __forceinline__ void ldsm_x4_t(uint32_t (&r)[4], uint32_t addr) {
    asm volatile("ldmatrix.sync.aligned.m8n8.x4.trans.shared.b16 {%0,%1,%2,%3}, [%4];"
        : "=r"(r[0]), "=r"(r[1]), "=r"(r[2]), "=r"(r[3]) : "r"(addr));
}
__device__ __forceinline__ void mma16816(float (&c)[4], const uint32_t (&a)[4],
                                         uint32_t b0, uint32_t b1) {
    asm volatile("mma.sync.aligned.m16n8k16.row.col.f32.bf16.bf16.f32 "
        "{%0,%1,%2,%3}, {%4,%5,%6,%7}, {%8,%9}, {%0,%1,%2,%3};"
        : "+f"(c[0]), "+f"(c[1]), "+f"(c[2]), "+f"(c[3])
        : "r"(a[0]), "r"(a[1]), "r"(a[2]), "r"(a[3]), "r"(b0), "r"(b1));
}
__device__ __forceinline__ void cp16(uint32_t dst, const void* src) {
    asm volatile("cp.async.cg.shared.global [%0], [%1], 16;" :: "r"(dst), "l"(src));
}
#define CP_COMMIT() asm volatile("cp.async.commit_group;" ::: "memory")
#define CP_WAIT0()  asm volatile("cp.async.wait_group 0;" ::: "memory")
#define CP_WAIT1()  asm volatile("cp.async.wait_group 1;" ::: "memory")

// fast split: cvt.rn.bf16x2 + residual
__device__ __forceinline__ void split_pack(float p0, float p1, uint32_t& hi, uint32_t& lo) {
    uint32_t H;
    asm("cvt.rn.bf16x2.f32 %0, %1, %2;" : "=r"(H) : "f"(p1), "f"(p0));
    float h0 = __uint_as_float(H << 16);
    float h1 = __uint_as_float(H & 0xffff0000u);
    float l0 = p0 - h0, l1 = p1 - h1;
    uint32_t L;
    asm("cvt.rn.bf16x2.f32 %0, %1, %2;" : "=r"(L) : "f"(l1), "f"(l0));
    hi = H; lo = L;
}
__device__ __forceinline__ void bf16split(float v, bf16& h, bf16& l) {
    h = __float2bfloat16_rn(v);
    l = __float2bfloat16_rn(v - __bfloat162float(h));
}

// ======================= conversion kernels ================================
__global__ void conv_x_split(const float* __restrict__ X) {
    int i = blockIdx.x * blockDim.x + threadIdx.x;     // float4 index
    float4 v = ((const float4*)X)[i];
    uint32_t h01, l01, h23, l23;
    split_pack(v.x, v.y, h01, l01);
    split_pack(v.z, v.w, h23, l23);
    ((uint32_t*)g_xhi)[i * 2]     = h01;
    ((uint32_t*)g_xhi)[i * 2 + 1] = h23;
    ((uint32_t*)g_xlo)[i * 2]     = l01;
    ((uint32_t*)g_xlo)[i * 2 + 1] = l23;
}

// transpose + split: W [K=1024][N] row-major  ->  Wt [N][1024]
template<int WHICH>  // 0: w_attn (N=3072), 1: w_proj (N=1024)
__global__ void conv_w_tsplit(const float* __restrict__ W, int N) {
    __shared__ float tile[32][33];
    int x = blockIdx.x * 32 + threadIdx.x;       // n
#pragma unroll
    for (int r = 0; r < 4; ++r) {
        int y = blockIdx.y * 32 + threadIdx.y + r * 8;   // k
        tile[threadIdx.y + r * 8][threadIdx.x] = W[(size_t)y * N + x];
    }
    __syncthreads();
    int k = blockIdx.y * 32 + threadIdx.x;
    bf16* Hi = (WHICH == 0) ? g_wahi : g_wphi;
    bf16* Lo = (WHICH == 0) ? g_walo : g_wplo;
#pragma unroll
    for (int r = 0; r < 4; ++r) {
        int n = blockIdx.x * 32 + threadIdx.y + r * 8;
        float v = tile[threadIdx.x][threadIdx.y + r * 8];
        bf16 h, l; bf16split(v, h, l);
        Hi[(size_t)n * 1024 + k] = h;
        Lo[(size_t)n * 1024 + k] = l;
    }
}

// ======================= HMMA split-bf16 GEMM ==============================
// C[M,N] = A[M,1024]@B[N,1024]^T via K'=3072 (hi*hi + lo*hi + hi*lo).
// Block 128x128, 8 warps (2x4), warp tile 64x32, BK=64 (128B SW128 rows),
// 3-stage cp.async pipeline, 2 CTAs/SM (16 warps/SM) for latency overlap.
#define GEMM_STAGE_BYTES 32768               // A 16K + B 16K
#define GEMM_SMEM_BYTES  (3 * GEMM_STAGE_BYTES)
#define NKC 48

template<int MODE>   // 0 = qkv (scatter split q/k/v), 1 = proj (dense fp32 out)
__global__ void __launch_bounds__(256, 2) hmma_gemm(
    const float* __restrict__ bias, float* __restrict__ out)
{
    extern __shared__ __align__(16) uint8_t sm[];
    const int t  = threadIdx.x;
    const int w  = t >> 5, l = t & 31;
    const int m0 = blockIdx.y * 128;
    const int n0 = blockIdx.x * 128;
    const int wm = (w & 1) * 64;
    const int wn = (w >> 1) * 32;

    const bf16* Ahi = (MODE == 0) ? g_xhi : g_chi;
    const bf16* Alo = (MODE == 0) ? g_xlo : g_clo;
    const bf16* Bhi = (MODE == 0) ? g_wahi : g_wphi;
    const bf16* Blo = (MODE == 0) ? g_walo : g_wplo;

    float acc[4][4][4];
#pragma unroll
    for (int i = 0; i < 4; ++i)
#pragma unroll
        for (int j = 0; j < 4; ++j)
#pragma unroll
            for (int v = 0; v < 4; ++v) acc[i][j][v] = 0.f;

    auto stage_load = [&](int kc, int st) {
        const int kg   = kc * 64;
        const int seg  = kg >> 10;
        const int koff = kg & 1023;
        const bf16* Asrc = (seg == 1) ? Alo : Ahi;
        const bf16* Bsrc = (seg == 2) ? Blo : Bhi;
        uint32_t sA = smem_u32(sm) + st * GEMM_STAGE_BYTES;
        uint32_t sB = sA + 16384;
#pragma unroll
        for (int i = 0; i < 4; ++i) {
            int idx = t + 256 * i;
            int row = idx >> 3, sg = idx & 7;
            cp16(sA + row * 128 + ((sg ^ (row & 7)) << 4),
                 Asrc + (size_t)(m0 + row) * 1024 + koff + sg * 8);
        }
#pragma unroll
        for (int i = 0; i < 4; ++i) {
            int idx = t + 256 * i;
            int row = idx >> 3, sg = idx & 7;
            cp16(sB + row * 128 + ((sg ^ (row & 7)) << 4),
                 Bsrc + (size_t)(n0 + row) * 1024 + koff + sg * 8);
        }
        CP_COMMIT();
    };

    stage_load(0, 0);
    stage_load(1, 1);

    for (int kc = 0; kc < NKC; ++kc) {
        if (kc == NKC - 1) { CP_WAIT0(); } else { CP_WAIT1(); }
        __syncthreads();
        if (kc + 2 < NKC) stage_load(kc + 2, (kc + 2) % 3);

        const uint32_t bA = smem_u32(sm) + (kc % 3) * GEMM_STAGE_BYTES;
        const uint32_t bB = bA + 16384;
#pragma unroll
        for (int kt = 0; kt < 4; ++kt) {
            uint32_t a[4][4];
#pragma unroll
            for (int mi = 0; mi < 4; ++mi) {
                int r = wm + 16 * mi + (l & 15);
                int c = 2 * kt + (l >> 4);
                ldsm_x4(a[mi], bA + r * 128 + ((c ^ (r & 7)) << 4));
            }
#pragma unroll
            for (int ni2 = 0; ni2 < 2; ++ni2) {
                uint32_t b[4];
                int r = wn + 16 * ni2 + (l & 7) + ((l >> 4) & 1) * 8;
                int c = 2 * kt + ((l >> 3) & 1);
                ldsm_x4(b, bB + r * 128 + ((c ^ (r & 7)) << 4));
#pragma unroll
                for (int mi = 0; mi < 4; ++mi) {
                    mma16816(acc[mi][2 * ni2],     a[mi], b[0], b[1]);
                    mma16816(acc[mi][2 * ni2 + 1], a[mi], b[2], b[3]);
                }
            }
        }
    }

    // ---------------- epilogue ----------------
    const int part = n0 >> 10;   // uniform per block (128 | 1024)
#pragma unroll
    for (int mi = 0; mi < 4; ++mi) {
#pragma unroll
        for (int ni = 0; ni < 4; ++ni) {
            int gr = m0 + wm + 16 * mi + (l >> 2);
            int gc = n0 + wn + 8 * ni + 2 * (l & 3);
            float b0 = bias[gc], b1 = bias[gc + 1];
#pragma unroll
            for (int h2 = 0; h2 < 2; ++h2) {
                int row = gr + 8 * h2;
                float v0 = acc[mi][ni][2 * h2]     + b0;
                float v1 = acc[mi][ni][2 * h2 + 1] + b1;
                if (MODE == 1) {
                    float2 o; o.x = v0; o.y = v1;
                    *(float2*)(out + (size_t)row * 1024 + gc) = o;
                } else {
                    int rem = gc & 1023;
                    int hh  = rem >> 6, dd = rem & 63;
                    int bb  = row >> 11, s = row & 2047;
                    size_t idx = (((size_t)(bb * 16 + hh) * 2048) + s) * 64 + dd;
                    if (part == 0) { v0 *= 0.125f; v1 *= 0.125f; }
                    uint32_t H, L;
                    split_pack(v0, v1, H, L);
                    bf16* dHi = (part == 0) ? g_qhi : ((part == 1) ? g_khi : g_vhi);
                    bf16* dLo = (part == 0) ? g_qlo : ((part == 1) ? g_klo : g_vlo);
                    *(uint32_t*)(dHi + idx) = H;
                    *(uint32_t*)(dLo + idx) = L;
                }
            }
        }
    }
}

// ======================= HMMA flash attention ==============================
// Block: (q-tile 128, bh). 256 threads = 8 warps; warp w owns q rows 16w..16w+15.
// k-tile 64, double-buffered cp.async K/V. Split bf16 ctx written directly.
__global__ void __launch_bounds__(256) attn_hmma()
{
    // 2 stages x (Kh,Kl,Vh,Vl) x 8KB
    __shared__ __align__(16) uint8_t sKV[2][4][8192];

    const int t  = threadIdx.x;
    const int w  = t >> 5, l = t & 31;
    const int qt = blockIdx.x;
    const int bh = blockIdx.y;
    const int q0 = qt * 128;

    const bf16* qh = g_qhi + (size_t)bh * S_LEN * HD;
    const bf16* ql = g_qlo + (size_t)bh * S_LEN * HD;
    const bf16* kh = g_khi + (size_t)bh * S_LEN * HD;
    const bf16* kl = g_klo + (size_t)bh * S_LEN * HD;
    const bf16* vh = g_vhi + (size_t)bh * S_LEN * HD;
    const bf16* vl = g_vlo + (size_t)bh * S_LEN * HD;

    // Q A-fragments (hi & lo) straight from gmem; live in regs
    uint32_t aQh[4][4], aQl[4][4];
    const int gr = q0 + w * 16 + (l >> 2);
#pragma unroll
    for (int t16 = 0; t16 < 4; ++t16) {
#pragma unroll
        for (int rg = 0; rg < 4; ++rg) {
            int row = gr + (rg & 1) * 8;
            int col = 16 * t16 + 2 * (l & 3) + (rg >> 1) * 8;
            aQh[t16][rg] = *(const uint32_t*)(qh + (size_t)row * HD + col);
            aQl[t16][rg] = *(const uint32_t*)(ql + (size_t)row * HD + col);
        }
    }

    float m_i[2] = {-1e30f, -1e30f};
    float l_i[2] = {0.f, 0.f};
    float o[8][4];
#pragma unroll
    for (int nf = 0; nf < 8; ++nf)
#pragma unroll
        for (int v = 0; v < 4; ++v) o[nf][v] = 0.f;

    auto load_tile = [&](int kt) {
        const int st = kt & 1;
        const int k0 = kt * 64;
#pragma unroll
        for (int i = 0; i < 2; ++i) {
            int idx = t + 256 * i;
            int row = idx >> 3, sg = idx & 7;
            uint32_t sw = row * 128 + ((sg ^ (row & 7)) << 4);
            size_t goff = (size_t)(k0 + row) * HD + sg * 8;
            cp16(smem_u32(sKV[st][0]) + sw, kh + goff);
            cp16(smem_u32(sKV[st][1]) + sw, kl + goff);
            cp16(smem_u32(sKV[st][2]) + sw, vh + goff);
            cp16(smem_u32(sKV[st][3]) + sw, vl + goff);
        }
        CP_COMMIT();
    };

    const int ktiles = 2 * qt + 2;
    load_tile(0);

    for (int kt = 0; kt < ktiles; ++kt) {
        const int k0 = kt * 64;
        if (kt + 1 < ktiles) { load_tile(kt + 1); CP_WAIT1(); }
        else                 { CP_WAIT0(); }
        __syncthreads();

        const int st = kt & 1;
        const uint32_t bKh = smem_u32(sKV[st][0]);
        const uint32_t bKl = smem_u32(sKV[st][1]);
        const uint32_t bVh = smem_u32(sKV[st][2]);
        const uint32_t bVl = smem_u32(sKV[st][3]);

        // warps whose rows are all below this k-tile skip compute
        if (k0 <= q0 + w * 16 + 15) {
            // ---- S = Q K^T (3-pass) ----
            float sc[8][4];
#pragma unroll
            for (int nf = 0; nf < 8; ++nf)
#pragma unroll
                for (int v = 0; v < 4; ++v) sc[nf][v] = 0.f;

#pragma unroll
            for (int t16 = 0; t16 < 4; ++t16) {
#pragma unroll
                for (int nfp = 0; nfp < 4; ++nfp) {
                    int r = 16 * nfp + (l & 7) + ((l >> 4) & 1) * 8;
                    int c = 2 * t16 + ((l >> 3) & 1);
                    uint32_t off = r * 128 + ((c ^ (r & 7)) << 4);
                    uint32_t kh4[4], kl4[4];
                    ldsm_x4(kh4, bKh + off);
                    ldsm_x4(kl4, bKl + off);
                    mma16816(sc[2 * nfp],     aQh[t16], kh4[0], kh4[1]);
                    mma16816(sc[2 * nfp],     aQh[t16], kl4[0], kl4[1]);
                    mma16816(sc[2 * nfp],     aQl[t16], kh4[0], kh4[1]);
                    mma16816(sc[2 * nfp + 1], aQh[t16], kh4[2], kh4[3]);
                    mma16816(sc[2 * nfp + 1], aQh[t16], kl4[2], kl4[3]);
                    mma16816(sc[2 * nfp + 1], aQl[t16], kh4[2], kh4[3]);
                }
            }

            // causal mask (only tiles overlapping this warp's diagonal)
            if (k0 + 63 > q0 + w * 16) {
#pragma unroll
                for (int nf = 0; nf < 8; ++nf)
#pragma unroll
                    for (int v = 0; v < 4; ++v) {
                        int kg = k0 + 8 * nf + 2 * (l & 3) + (v & 1);
                        int qg = gr + 8 * (v >> 1);
                        if (kg > qg) sc[nf][v] = -1e30f;
                    }
            }

            // ---- online softmax ----
#pragma unroll
            for (int h = 0; h < 2; ++h) {
                float mt = -1e30f;
#pragma unroll
                for (int nf = 0; nf < 8; ++nf) {
                    mt = fmaxf(mt, sc[nf][2 * h]);
                    mt = fmaxf(mt, sc[nf][2 * h + 1]);
                }
                mt = fmaxf(mt, __shfl_xor_sync(0xffffffffu, mt, 1));
                mt = fmaxf(mt, __shfl_xor_sync(0xffffffffu, mt, 2));
                float mnew = fmaxf(m_i[h], mt);
                float corr = __expf(m_i[h] - mnew);
                float psum = 0.f;
#pragma unroll
                for (int nf = 0; nf < 8; ++nf) {
                    float p0 = __expf(sc[nf][2 * h]     - mnew);
                    float p1 = __expf(sc[nf][2 * h + 1] - mnew);
                    sc[nf][2 * h] = p0; sc[nf][2 * h + 1] = p1;
                    psum += p0 + p1;
                }
                psum += __shfl_xor_sync(0xffffffffu, psum, 1);
                psum += __shfl_xor_sync(0xffffffffu, psum, 2);
                l_i[h] = l_i[h] * corr + psum;
                m_i[h] = mnew;
#pragma unroll
                for (int nf = 0; nf < 8; ++nf) {
                    o[nf][2 * h]     *= corr;
                    o[nf][2 * h + 1] *= corr;
                }
            }

            // ---- repack P as split A-frags ----
            uint32_t aPh[4][4], aPl[4][4];
#pragma unroll
            for (int t16 = 0; t16 < 4; ++t16) {
                split_pack(sc[2 * t16][0],     sc[2 * t16][1],     aPh[t16][0], aPl[t16][0]);
                split_pack(sc[2 * t16][2],     sc[2 * t16][3],     aPh[t16][1], aPl[t16][1]);
                split_pack(sc[2 * t16 + 1][0], sc[2 * t16 + 1][1], aPh[t16][2], aPl[t16][2]);
                split_pack(sc[2 * t16 + 1][2], sc[2 * t16 + 1][3], aPh[t16][3], aPl[t16][3]);
            }

            // ---- O += P V (3-pass, V transposed via ldmatrix.trans) ----
#pragma unroll
            for (int t16 = 0; t16 < 4; ++t16) {
#pragma unroll
                for (int nfp = 0; nfp < 4; ++nfp) {
                    int r = 16 * t16 + (l & 7) + ((l >> 3) & 1) * 8;
                    int c = 2 * nfp + ((l >> 4) & 1);
                    uint32_t off = r * 128 + ((c ^ (r & 7)) << 4);
                    uint32_t vh4[4], vl4[4];
                    ldsm_x4_t(vh4, bVh + off);
                    ldsm_x4_t(vl4, bVl + off);
                    mma16816(o[2 * nfp],     aPh[t16], vh4[0], vh4[1]);
                    mma16816(o[2 * nfp],     aPh[t16], vl4[0], vl4[1]);
                    mma16816(o[2 * nfp],     aPl[t16], vh4[0], vh4[1]);
                    mma16816(o[2 * nfp + 1], aPh[t16], vh4[2], vh4[3]);
                    mma16816(o[2 * nfp + 1], aPh[t16], vl4[2], vl4[3]);
                    mma16816(o[2 * nfp + 1], aPl[t16], vh4[2], vh4[3]);
                }
            }
        }
        __syncthreads();   // stage reads done before it is overwritten
    }

    // ---- epilogue: normalize, split, write ctx as bf16 hi/lo ----
    const int bb = bh >> 4, hh = bh & 15;
#pragma unroll
    for (int h = 0; h < 2; ++h) {
        float inv = 1.f / l_i[h];
        int row = gr + 8 * h;
#pragma unroll
        for (int nf = 0; nf < 8; ++nf) {
            int d = 8 * nf + 2 * (l & 3);
            size_t idx = ((size_t)(bb * S_LEN + row)) * D_MODEL + hh * HD + d;
            uint32_t H, L;
            split_pack(o[nf][2 * h] * inv, o[nf][2 * h + 1] * inv, H, L);
            *(uint32_t*)(g_chi + idx) = H;
            *(uint32_t*)(g_clo + idx) = L;
        }
    }
}

// ===========================================================================
extern "C" void kernel_launch(void* const* d_in, const int* in_sizes, int n_in,
                              void* d_out, int out_size)
{
    const float* X  = (const float*)d_in[0];   // hidden_states [2,2048,1024]
    const float* Wa = (const float*)d_in[1];   // w_attn [1024,3072]
    const float* ba = (const float*)d_in[2];   // b_attn [3072]
    const float* Wp = (const float*)d_in[3];   // w_proj [1024,1024]
    const float* bp = (const float*)d_in[4];   // b_proj [1024]
    float* out = (float*)d_out;                // [2,2048,1024]

    cudaFuncSetAttribute(hmma_gemm<0>,
                         cudaFuncAttributeMaxDynamicSharedMemorySize, GEMM_SMEM_BYTES);
    cudaFuncSetAttribute(hmma_gemm<1>,
                         cudaFuncAttributeMaxDynamicSharedMemorySize, GEMM_SMEM_BYTES);

    conv_x_split<<<(M_TOT * D_MODEL / 4) / 256, 256>>>(X);
    conv_w_tsplit<0><<<dim3(96, 32), dim3(32, 8)>>>(Wa, 3072);
    conv_w_tsplit<1><<<dim3(32, 32), dim3(32, 8)>>>(Wp, 1024);

    hmma_gemm<0><<<dim3(24, 32), 256, GEMM_SMEM_BYTES>>>(ba, out);
    attn_hmma<<<dim3(16, 32), 256>>>();
    hmma_gemm<1><<<dim3(8, 32), 256, GEMM_SMEM_BYTES>>>(bp, out);
}

// round 7
// speedup vs baseline: 1.0711x; 1.0711x over previous
#include <cuda_runtime.h>
#include <cuda_bf16.h>
#include <cstdint>

#define B_SZ    2
#define S_LEN   2048
#define D_MODEL 1024
#define N_HEADS 16
#define HD      64
#define M_TOT   (B_SZ * S_LEN)   // 4096

typedef __nv_bfloat16 bf16;
typedef __nv_bfloat162 bf162;

// ---------------- scratch (device globals; no allocation allowed) ----------
__device__ bf16 g_xhi[M_TOT * D_MODEL];               // hidden split
__device__ bf16 g_xlo[M_TOT * D_MODEL];
__device__ bf16 g_wahi[3 * D_MODEL * D_MODEL];        // w_attn^T split [3072][1024]
__device__ bf16 g_walo[3 * D_MODEL * D_MODEL];
__device__ bf16 g_wphi[D_MODEL * D_MODEL];            // w_proj^T split [1024][1024]
__device__ bf16 g_wplo[D_MODEL * D_MODEL];
__device__ bf16 g_chi[M_TOT * D_MODEL];               // ctx split (written by attn)
__device__ bf16 g_clo[M_TOT * D_MODEL];

// attention operands, split bf16, layout [B,H,S,hd]
__device__ bf16 g_qhi[B_SZ * N_HEADS * S_LEN * HD];   // pre-scaled by 0.125
__device__ bf16 g_qlo[B_SZ * N_HEADS * S_LEN * HD];
__device__ bf16 g_khi[B_SZ * N_HEADS * S_LEN * HD];
__device__ bf16 g_klo[B_SZ * N_HEADS * S_LEN * HD];
__device__ bf16 g_vhi[B_SZ * N_HEADS * S_LEN * HD];
__device__ bf16 g_vlo[B_SZ * N_HEADS * S_LEN * HD];

// ======================= helpers ===========================================
__device__ __forceinline__ uint32_t smem_u32(const void* p) {
    uint32_t a;
    asm("{ .reg .u64 t; cvta.to.shared.u64 t, %1; cvt.u32.u64 %0, t; }" : "=r"(a) : "l"(p));
    return a;
}
__device__ __forceinline__ void ldsm_x4(uint32_t (&r)[4], uint32_t addr) {
    asm volatile("ldmatrix.sync.aligned.m8n8.x4.shared.b16 {%0,%1,%2,%3}, [%4];"
        : "=r"(r[0]), "=r"(r[1]), "=r"(r[2]), "=r"(r[3]) : "r"(addr));
}
__device__ __forceinline__ void ldsm_x4_t(uint32_t (&r)[4], uint32_t addr) {
    asm volatile("ldmatrix.sync.aligned.m8n8.x4.trans.shared.b16 {%0,%1,%2,%3}, [%4];"
        : "=r"(r[0]), "=r"(r[1]), "=r"(r[2]), "=r"(r[3]) : "r"(addr));
}
__device__ __forceinline__ void mma16816(float (&c)[4], const uint32_t (&a)[4],
                                         uint32_t b0, uint32_t b1) {
    asm volatile("mma.sync.aligned.m16n8k16.row.col.f32.bf16.bf16.f32 "
        "{%0,%1,%2,%3}, {%4,%5,%6,%7}, {%8,%9}, {%0,%1,%2,%3};"
        : "+f"(c[0]), "+f"(c[1]), "+f"(c[2]), "+f"(c[3])
        : "r"(a[0]), "r"(a[1]), "r"(a[2]), "r"(a[3]), "r"(b0), "r"(b1));
}
__device__ __forceinline__ void cp16(uint32_t dst, const void* src) {
    asm volatile("cp.async.cg.shared.global [%0], [%1], 16;" :: "r"(dst), "l"(src));
}
#define CP_COMMIT() asm volatile("cp.async.commit_group;" ::: "memory")
#define CP_WAIT0()  asm volatile("cp.async.wait_group 0;" ::: "memory")
#define CP_WAIT1()  asm volatile("cp.async.wait_group 1;" ::: "memory")

// fast split: cvt.rn.bf16x2 + residual
__device__ __forceinline__ void split_pack(float p0, float p1, uint32_t& hi, uint32_t& lo) {
    uint32_t H;
    asm("cvt.rn.bf16x2.f32 %0, %1, %2;" : "=r"(H) : "f"(p1), "f"(p0));
    float h0 = __uint_as_float(H << 16);
    float h1 = __uint_as_float(H & 0xffff0000u);
    float l0 = p0 - h0, l1 = p1 - h1;
    uint32_t L;
    asm("cvt.rn.bf16x2.f32 %0, %1, %2;" : "=r"(L) : "f"(l1), "f"(l0));
    hi = H; lo = L;
}
__device__ __forceinline__ void bf16split(float v, bf16& h, bf16& l) {
    h = __float2bfloat16_rn(v);
    l = __float2bfloat16_rn(v - __bfloat162float(h));
}

// ======================= conversion kernels ================================
__global__ void conv_x_split(const float* __restrict__ X) {
    int i = blockIdx.x * blockDim.x + threadIdx.x;     // float4 index
    float4 v = ((const float4*)X)[i];
    uint32_t h01, l01, h23, l23;
    split_pack(v.x, v.y, h01, l01);
    split_pack(v.z, v.w, h23, l23);
    ((uint32_t*)g_xhi)[i * 2]     = h01;
    ((uint32_t*)g_xhi)[i * 2 + 1] = h23;
    ((uint32_t*)g_xlo)[i * 2]     = l01;
    ((uint32_t*)g_xlo)[i * 2 + 1] = l23;
}

// transpose + split: W [K=1024][N] row-major  ->  Wt [N][1024]
template<int WHICH>  // 0: w_attn (N=3072), 1: w_proj (N=1024)
__global__ void conv_w_tsplit(const float* __restrict__ W, int N) {
    __shared__ float tile[32][33];
    int x = blockIdx.x * 32 + threadIdx.x;       // n
#pragma unroll
    for (int r = 0; r < 4; ++r) {
        int y = blockIdx.y * 32 + threadIdx.y + r * 8;   // k
        tile[threadIdx.y + r * 8][threadIdx.x] = W[(size_t)y * N + x];
    }
    __syncthreads();
    int k = blockIdx.y * 32 + threadIdx.x;
    bf16* Hi = (WHICH == 0) ? g_wahi : g_wphi;
    bf16* Lo = (WHICH == 0) ? g_walo : g_wplo;
#pragma unroll
    for (int r = 0; r < 4; ++r) {
        int n = blockIdx.x * 32 + threadIdx.y + r * 8;
        float v = tile[threadIdx.x][threadIdx.y + r * 8];
        bf16 h, l; bf16split(v, h, l);
        Hi[(size_t)n * 1024 + k] = h;
        Lo[(size_t)n * 1024 + k] = l;
    }
}

// ======================= HMMA split-bf16 GEMM (R5 config) ==================
// C[M,N] = A[M,1024]@B[N,1024]^T via K'=3072 (hi*hi + lo*hi + hi*lo).
// Block 128x128, 4 warps (2x2), warp tile 64x64, BK=64 (128B SW128 rows),
// 3-stage cp.async pipeline, 2 CTAs/SM.
#define GEMM_STAGE_BYTES 32768               // A 16K + B 16K
#define GEMM_SMEM_BYTES  (3 * GEMM_STAGE_BYTES)
#define NKC 48

template<int MODE>   // 0 = qkv (scatter split q/k/v), 1 = proj (dense fp32 out)
__global__ void __launch_bounds__(128, 2) hmma_gemm(
    const float* __restrict__ bias, float* __restrict__ out)
{
    extern __shared__ __align__(16) uint8_t sm[];
    const int t  = threadIdx.x;
    const int w  = t >> 5, l = t & 31;
    const int m0 = blockIdx.y * 128;
    const int n0 = blockIdx.x * 128;
    const int wm = (w & 1) * 64;
    const int wn = (w >> 1) * 64;

    const bf16* Ahi = (MODE == 0) ? g_xhi : g_chi;
    const bf16* Alo = (MODE == 0) ? g_xlo : g_clo;
    const bf16* Bhi = (MODE == 0) ? g_wahi : g_wphi;
    const bf16* Blo = (MODE == 0) ? g_walo : g_wplo;

    float acc[4][8][4];
#pragma unroll
    for (int i = 0; i < 4; ++i)
#pragma unroll
        for (int j = 0; j < 8; ++j)
#pragma unroll
            for (int v = 0; v < 4; ++v) acc[i][j][v] = 0.f;

    auto stage_load = [&](int kc, int st) {
        const int kg   = kc * 64;
        const int seg  = kg >> 10;
        const int koff = kg & 1023;
        const bf16* Asrc = (seg == 1) ? Alo : Ahi;
        const bf16* Bsrc = (seg == 2) ? Blo : Bhi;
        uint32_t sA = smem_u32(sm) + st * GEMM_STAGE_BYTES;
        uint32_t sB = sA + 16384;
#pragma unroll
        for (int i = 0; i < 8; ++i) {
            int idx = t + 128 * i;
            int row = idx >> 3, sg = idx & 7;
            cp16(sA + row * 128 + ((sg ^ (row & 7)) << 4),
                 Asrc + (size_t)(m0 + row) * 1024 + koff + sg * 8);
        }
#pragma unroll
        for (int i = 0; i < 8; ++i) {
            int idx = t + 128 * i;
            int row = idx >> 3, sg = idx & 7;
            cp16(sB + row * 128 + ((sg ^ (row & 7)) << 4),
                 Bsrc + (size_t)(n0 + row) * 1024 + koff + sg * 8);
        }
        CP_COMMIT();
    };

    stage_load(0, 0);
    stage_load(1, 1);

    for (int kc = 0; kc < NKC; ++kc) {
        if (kc == NKC - 1) { CP_WAIT0(); } else { CP_WAIT1(); }
        __syncthreads();
        if (kc + 2 < NKC) stage_load(kc + 2, (kc + 2) % 3);

        const uint32_t bA = smem_u32(sm) + (kc % 3) * GEMM_STAGE_BYTES;
        const uint32_t bB = bA + 16384;
#pragma unroll
        for (int kt = 0; kt < 4; ++kt) {
            uint32_t a[4][4];
#pragma unroll
            for (int mi = 0; mi < 4; ++mi) {
                int r = wm + 16 * mi + (l & 15);
                int c = 2 * kt + (l >> 4);
                ldsm_x4(a[mi], bA + r * 128 + ((c ^ (r & 7)) << 4));
            }
#pragma unroll
            for (int ni2 = 0; ni2 < 4; ++ni2) {
                uint32_t b[4];
                int r = wn + 16 * ni2 + (l & 7) + ((l >> 4) & 1) * 8;
                int c = 2 * kt + ((l >> 3) & 1);
                ldsm_x4(b, bB + r * 128 + ((c ^ (r & 7)) << 4));
#pragma unroll
                for (int mi = 0; mi < 4; ++mi) {
                    mma16816(acc[mi][2 * ni2],     a[mi], b[0], b[1]);
                    mma16816(acc[mi][2 * ni2 + 1], a[mi], b[2], b[3]);
                }
            }
        }
    }

    // ---------------- epilogue ----------------
    const int part = n0 >> 10;   // uniform per block (128 | 1024)
#pragma unroll
    for (int mi = 0; mi < 4; ++mi) {
#pragma unroll
        for (int ni = 0; ni < 8; ++ni) {
            int gr = m0 + wm + 16 * mi + (l >> 2);
            int gc = n0 + wn + 8 * ni + 2 * (l & 3);
            float b0 = bias[gc], b1 = bias[gc + 1];
#pragma unroll
            for (int h2 = 0; h2 < 2; ++h2) {
                int row = gr + 8 * h2;
                float v0 = acc[mi][ni][2 * h2]     + b0;
                float v1 = acc[mi][ni][2 * h2 + 1] + b1;
                if (MODE == 1) {
                    float2 o; o.x = v0; o.y = v1;
                    *(float2*)(out + (size_t)row * 1024 + gc) = o;
                } else {
                    int rem = gc & 1023;
                    int hh  = rem >> 6, dd = rem & 63;
                    int bb  = row >> 11, s = row & 2047;
                    size_t idx = (((size_t)(bb * 16 + hh) * 2048) + s) * 64 + dd;
                    if (part == 0) { v0 *= 0.125f; v1 *= 0.125f; }
                    uint32_t H, L;
                    split_pack(v0, v1, H, L);
                    bf16* dHi = (part == 0) ? g_qhi : ((part == 1) ? g_khi : g_vhi);
                    bf16* dLo = (part == 0) ? g_qlo : ((part == 1) ? g_klo : g_vlo);
                    *(uint32_t*)(dHi + idx) = H;
                    *(uint32_t*)(dLo + idx) = L;
                }
            }
        }
    }
}

// ======================= HMMA flash attention ==============================
// Block: (q-tile 64, bh). 128 threads = 4 warps (2 CTAs/SM); warp w owns q rows
// 16w..16w+15. k-tile 64, double-buffered cp.async K/V. Split bf16 ctx out.
__global__ void __launch_bounds__(128) attn_hmma()
{
    // 2 stages x (Kh,Kl,Vh,Vl) x 8KB = 64KB
    __shared__ __align__(16) uint8_t sKV[2][4][8192];

    const int t  = threadIdx.x;
    const int w  = t >> 5, l = t & 31;
    const int qt = blockIdx.x;
    const int bh = blockIdx.y;
    const int q0 = qt * 64;

    const bf16* qh = g_qhi + (size_t)bh * S_LEN * HD;
    const bf16* ql = g_qlo + (size_t)bh * S_LEN * HD;
    const bf16* kh = g_khi + (size_t)bh * S_LEN * HD;
    const bf16* kl = g_klo + (size_t)bh * S_LEN * HD;
    const bf16* vh = g_vhi + (size_t)bh * S_LEN * HD;
    const bf16* vl = g_vlo + (size_t)bh * S_LEN * HD;

    // Q A-fragments (hi & lo) straight from gmem; live in regs
    uint32_t aQh[4][4], aQl[4][4];
    const int gr = q0 + w * 16 + (l >> 2);
#pragma unroll
    for (int t16 = 0; t16 < 4; ++t16) {
#pragma unroll
        for (int rg = 0; rg < 4; ++rg) {
            int row = gr + (rg & 1) * 8;
            int col = 16 * t16 + 2 * (l & 3) + (rg >> 1) * 8;
            aQh[t16][rg] = *(const uint32_t*)(qh + (size_t)row * HD + col);
            aQl[t16][rg] = *(const uint32_t*)(ql + (size_t)row * HD + col);
        }
    }

    float m_i[2] = {-1e30f, -1e30f};
    float l_i[2] = {0.f, 0.f};
    float o[8][4];
#pragma unroll
    for (int nf = 0; nf < 8; ++nf)
#pragma unroll
        for (int v = 0; v < 4; ++v) o[nf][v] = 0.f;

    auto load_tile = [&](int kt) {
        const int st = kt & 1;
        const int k0 = kt * 64;
#pragma unroll
        for (int i = 0; i < 4; ++i) {
            int idx = t + 128 * i;
            int row = idx >> 3, sg = idx & 7;
            uint32_t sw = row * 128 + ((sg ^ (row & 7)) << 4);
            size_t goff = (size_t)(k0 + row) * HD + sg * 8;
            cp16(smem_u32(sKV[st][0]) + sw, kh + goff);
            cp16(smem_u32(sKV[st][1]) + sw, kl + goff);
            cp16(smem_u32(sKV[st][2]) + sw, vh + goff);
            cp16(smem_u32(sKV[st][3]) + sw, vl + goff);
        }
        CP_COMMIT();
    };

    const int ktiles = qt + 1;
    load_tile(0);

    for (int kt = 0; kt < ktiles; ++kt) {
        const int k0 = kt * 64;
        if (kt + 1 < ktiles) { load_tile(kt + 1); CP_WAIT1(); }
        else                 { CP_WAIT0(); }
        __syncthreads();

        const int st = kt & 1;
        const uint32_t bKh = smem_u32(sKV[st][0]);
        const uint32_t bKl = smem_u32(sKV[st][1]);
        const uint32_t bVh = smem_u32(sKV[st][2]);
        const uint32_t bVl = smem_u32(sKV[st][3]);

        // warps whose rows are all below this k-tile skip compute
        if (k0 <= q0 + w * 16 + 15) {
            // ---- S = Q K^T (3-pass) ----
            float sc[8][4];
#pragma unroll
            for (int nf = 0; nf < 8; ++nf)
#pragma unroll
                for (int v = 0; v < 4; ++v) sc[nf][v] = 0.f;

#pragma unroll
            for (int t16 = 0; t16 < 4; ++t16) {
#pragma unroll
                for (int nfp = 0; nfp < 4; ++nfp) {
                    int r = 16 * nfp + (l & 7) + ((l >> 4) & 1) * 8;
                    int c = 2 * t16 + ((l >> 3) & 1);
                    uint32_t off = r * 128 + ((c ^ (r & 7)) << 4);
                    uint32_t kh4[4], kl4[4];
                    ldsm_x4(kh4, bKh + off);
                    ldsm_x4(kl4, bKl + off);
                    mma16816(sc[2 * nfp],     aQh[t16], kh4[0], kh4[1]);
                    mma16816(sc[2 * nfp],     aQh[t16], kl4[0], kl4[1]);
                    mma16816(sc[2 * nfp],     aQl[t16], kh4[0], kh4[1]);
                    mma16816(sc[2 * nfp + 1], aQh[t16], kh4[2], kh4[3]);
                    mma16816(sc[2 * nfp + 1], aQh[t16], kl4[2], kl4[3]);
                    mma16816(sc[2 * nfp + 1], aQl[t16], kh4[2], kh4[3]);
                }
            }

            // causal mask (only tiles overlapping this warp's diagonal)
            if (k0 + 63 > q0 + w * 16) {
#pragma unroll
                for (int nf = 0; nf < 8; ++nf)
#pragma unroll
                    for (int v = 0; v < 4; ++v) {
                        int kg = k0 + 8 * nf + 2 * (l & 3) + (v & 1);
                        int qg = gr + 8 * (v >> 1);
                        if (kg > qg) sc[nf][v] = -1e30f;
                    }
            }

            // ---- online softmax ----
#pragma unroll
            for (int h = 0; h < 2; ++h) {
                float mt = -1e30f;
#pragma unroll
                for (int nf = 0; nf < 8; ++nf) {
                    mt = fmaxf(mt, sc[nf][2 * h]);
                    mt = fmaxf(mt, sc[nf][2 * h + 1]);
                }
                mt = fmaxf(mt, __shfl_xor_sync(0xffffffffu, mt, 1));
                mt = fmaxf(mt, __shfl_xor_sync(0xffffffffu, mt, 2));
                float mnew = fmaxf(m_i[h], mt);
                float corr = __expf(m_i[h] - mnew);
                float psum = 0.f;
#pragma unroll
                for (int nf = 0; nf < 8; ++nf) {
                    float p0 = __expf(sc[nf][2 * h]     - mnew);
                    float p1 = __expf(sc[nf][2 * h + 1] - mnew);
                    sc[nf][2 * h] = p0; sc[nf][2 * h + 1] = p1;
                    psum += p0 + p1;
                }
                psum += __shfl_xor_sync(0xffffffffu, psum, 1);
                psum += __shfl_xor_sync(0xffffffffu, psum, 2);
                l_i[h] = l_i[h] * corr + psum;
                m_i[h] = mnew;
#pragma unroll
                for (int nf = 0; nf < 8; ++nf) {
                    o[nf][2 * h]     *= corr;
                    o[nf][2 * h + 1] *= corr;
                }
            }

            // ---- repack P as split A-frags ----
            uint32_t aPh[4][4], aPl[4][4];
#pragma unroll
            for (int t16 = 0; t16 < 4; ++t16) {
                split_pack(sc[2 * t16][0],     sc[2 * t16][1],     aPh[t16][0], aPl[t16][0]);
                split_pack(sc[2 * t16][2],     sc[2 * t16][3],     aPh[t16][1], aPl[t16][1]);
                split_pack(sc[2 * t16 + 1][0], sc[2 * t16 + 1][1], aPh[t16][2], aPl[t16][2]);
                split_pack(sc[2 * t16 + 1][2], sc[2 * t16 + 1][3], aPh[t16][3], aPl[t16][3]);
            }

            // ---- O += P V (3-pass, V transposed via ldmatrix.trans) ----
#pragma unroll
            for (int t16 = 0; t16 < 4; ++t16) {
#pragma unroll
                for (int nfp = 0; nfp < 4; ++nfp) {
                    int r = 16 * t16 + (l & 7) + ((l >> 3) & 1) * 8;
                    int c = 2 * nfp + ((l >> 4) & 1);
                    uint32_t off = r * 128 + ((c ^ (r & 7)) << 4);
                    uint32_t vh4[4], vl4[4];
                    ldsm_x4_t(vh4, bVh + off);
                    ldsm_x4_t(vl4, bVl + off);
                    mma16816(o[2 * nfp],     aPh[t16], vh4[0], vh4[1]);
                    mma16816(o[2 * nfp],     aPh[t16], vl4[0], vl4[1]);
                    mma16816(o[2 * nfp],     aPl[t16], vh4[0], vh4[1]);
                    mma16816(o[2 * nfp + 1], aPh[t16], vh4[2], vh4[3]);
                    mma16816(o[2 * nfp + 1], aPh[t16], vl4[2], vl4[3]);
                    mma16816(o[2 * nfp + 1], aPl[t16], vh4[2], vh4[3]);
                }
            }
        }
        __syncthreads();   // stage reads done before it is overwritten
    }

    // ---- epilogue: normalize, split, write ctx as bf16 hi/lo ----
    const int bb = bh >> 4, hh = bh & 15;
#pragma unroll
    for (int h = 0; h < 2; ++h) {
        float inv = 1.f / l_i[h];
        int row = gr + 8 * h;
#pragma unroll
        for (int nf = 0; nf < 8; ++nf) {
            int d = 8 * nf + 2 * (l & 3);
            size_t idx = ((size_t)(bb * S_LEN + row)) * D_MODEL + hh * HD + d;
            uint32_t H, L;
            split_pack(o[nf][2 * h] * inv, o[nf][2 * h + 1] * inv, H, L);
            *(uint32_t*)(g_chi + idx) = H;
            *(uint32_t*)(g_clo + idx) = L;
        }
    }
}

// ===========================================================================
extern "C" void kernel_launch(void* const* d_in, const int* in_sizes, int n_in,
                              void* d_out, int out_size)
{
    const float* X  = (const float*)d_in[0];   // hidden_states [2,2048,1024]
    const float* Wa = (const float*)d_in[1];   // w_attn [1024,3072]
    const float* ba = (const float*)d_in[2];   // b_attn [3072]
    const float* Wp = (const float*)d_in[3];   // w_proj [1024,1024]
    const float* bp = (const float*)d_in[4];   // b_proj [1024]
    float* out = (float*)d_out;                // [2,2048,1024]

    cudaFuncSetAttribute(hmma_gemm<0>,
                         cudaFuncAttributeMaxDynamicSharedMemorySize, GEMM_SMEM_BYTES);
    cudaFuncSetAttribute(hmma_gemm<1>,
                         cudaFuncAttributeMaxDynamicSharedMemorySize, GEMM_SMEM_BYTES);

    conv_x_split<<<(M_TOT * D_MODEL / 4) / 256, 256>>>(X);
    conv_w_tsplit<0><<<dim3(96, 32), dim3(32, 8)>>>(Wa, 3072);
    conv_w_tsplit<1><<<dim3(32, 32), dim3(32, 8)>>>(Wp, 1024);

    hmma_gemm<0><<<dim3(24, 32), 128, GEMM_SMEM_BYTES>>>(ba, out);
    attn_hmma<<<dim3(32, 32), 128>>>();
    hmma_gemm<1><<<dim3(8, 32), 128, GEMM_SMEM_BYTES>>>(bp, out);
}

// round 8
// speedup vs baseline: 1.0968x; 1.0240x over previous
#include <cuda_runtime.h>
#include <cuda_bf16.h>
#include <cstdint>

#define B_SZ    2
#define S_LEN   2048
#define D_MODEL 1024
#define N_HEADS 16
#define HD      64
#define M_TOT   (B_SZ * S_LEN)   // 4096

typedef __nv_bfloat16 bf16;
typedef __nv_bfloat162 bf162;

// ---------------- scratch (device globals; no allocation allowed) ----------
__device__ bf16 g_xhi[M_TOT * D_MODEL];               // hidden split
__device__ bf16 g_xlo[M_TOT * D_MODEL];
__device__ bf16 g_wahi[3 * D_MODEL * D_MODEL];        // w_attn^T split [3072][1024]
__device__ bf16 g_walo[3 * D_MODEL * D_MODEL];
__device__ bf16 g_wphi[D_MODEL * D_MODEL];            // w_proj^T split [1024][1024]
__device__ bf16 g_wplo[D_MODEL * D_MODEL];
__device__ bf16 g_chi[M_TOT * D_MODEL];               // ctx split (written by attn)
__device__ bf16 g_clo[M_TOT * D_MODEL];

// attention operands, split bf16, layout [B,H,S,hd]
__device__ bf16 g_qhi[B_SZ * N_HEADS * S_LEN * HD];   // pre-scaled by 0.125
__device__ bf16 g_qlo[B_SZ * N_HEADS * S_LEN * HD];
__device__ bf16 g_khi[B_SZ * N_HEADS * S_LEN * HD];
__device__ bf16 g_klo[B_SZ * N_HEADS * S_LEN * HD];
__device__ bf16 g_vhi[B_SZ * N_HEADS * S_LEN * HD];
__device__ bf16 g_vlo[B_SZ * N_HEADS * S_LEN * HD];

// ======================= helpers ===========================================
__device__ __forceinline__ uint32_t smem_u32(const void* p) {
    uint32_t a;
    asm("{ .reg .u64 t; cvta.to.shared.u64 t, %1; cvt.u32.u64 %0, t; }" : "=r"(a) : "l"(p));
    return a;
}
__device__ __forceinline__ void ldsm_x4(uint32_t (&r)[4], uint32_t addr) {
    asm volatile("ldmatrix.sync.aligned.m8n8.x4.shared.b16 {%0,%1,%2,%3}, [%4];"
        : "=r"(r[0]), "=r"(r[1]), "=r"(r[2]), "=r"(r[3]) : "r"(addr));
}
__device__ __forceinline__ void ldsm_x4_t(uint32_t (&r)[4], uint32_t addr) {
    asm volatile("ldmatrix.sync.aligned.m8n8.x4.trans.shared.b16 {%0,%1,%2,%3}, [%4];"
        : "=r"(r[0]), "=r"(r[1]), "=r"(r[2]), "=r"(r[3]) : "r"(addr));
}
__device__ __forceinline__ void mma16816(float (&c)[4], const uint32_t (&a)[4],
                                         uint32_t b0, uint32_t b1) {
    asm volatile("mma.sync.aligned.m16n8k16.row.col.f32.bf16.bf16.f32 "
        "{%0,%1,%2,%3}, {%4,%5,%6,%7}, {%8,%9}, {%0,%1,%2,%3};"
        : "+f"(c[0]), "+f"(c[1]), "+f"(c[2]), "+f"(c[3])
        : "r"(a[0]), "r"(a[1]), "r"(a[2]), "r"(a[3]), "r"(b0), "r"(b1));
}
__device__ __forceinline__ void cp16(uint32_t dst, const void* src) {
    asm volatile("cp.async.cg.shared.global [%0], [%1], 16;" :: "r"(dst), "l"(src));
}
#define CP_COMMIT() asm volatile("cp.async.commit_group;" ::: "memory")
#define CP_WAIT0()  asm volatile("cp.async.wait_group 0;" ::: "memory")
#define CP_WAIT1()  asm volatile("cp.async.wait_group 1;" ::: "memory")

// fast split: cvt.rn.bf16x2 + residual
__device__ __forceinline__ void split_pack(float p0, float p1, uint32_t& hi, uint32_t& lo) {
    uint32_t H;
    asm("cvt.rn.bf16x2.f32 %0, %1, %2;" : "=r"(H) : "f"(p1), "f"(p0));
    float h0 = __uint_as_float(H << 16);
    float h1 = __uint_as_float(H & 0xffff0000u);
    float l0 = p0 - h0, l1 = p1 - h1;
    uint32_t L;
    asm("cvt.rn.bf16x2.f32 %0, %1, %2;" : "=r"(L) : "f"(l1), "f"(l0));
    hi = H; lo = L;
}
__device__ __forceinline__ void bf16split(float v, bf16& h, bf16& l) {
    h = __float2bfloat16_rn(v);
    l = __float2bfloat16_rn(v - __bfloat162float(h));
}

// ======================= conversion kernels ================================
__global__ void conv_x_split(const float* __restrict__ X) {
    int i = blockIdx.x * blockDim.x + threadIdx.x;     // float4 index
    float4 v = ((const float4*)X)[i];
    uint32_t h01, l01, h23, l23;
    split_pack(v.x, v.y, h01, l01);
    split_pack(v.z, v.w, h23, l23);
    ((uint32_t*)g_xhi)[i * 2]     = h01;
    ((uint32_t*)g_xhi)[i * 2 + 1] = h23;
    ((uint32_t*)g_xlo)[i * 2]     = l01;
    ((uint32_t*)g_xlo)[i * 2 + 1] = l23;
}

// transpose + split: W [K=1024][N] row-major  ->  Wt [N][1024]
template<int WHICH>  // 0: w_attn (N=3072), 1: w_proj (N=1024)
__global__ void conv_w_tsplit(const float* __restrict__ W, int N) {
    __shared__ float tile[32][33];
    int x = blockIdx.x * 32 + threadIdx.x;       // n
#pragma unroll
    for (int r = 0; r < 4; ++r) {
        int y = blockIdx.y * 32 + threadIdx.y + r * 8;   // k
        tile[threadIdx.y + r * 8][threadIdx.x] = W[(size_t)y * N + x];
    }
    __syncthreads();
    int k = blockIdx.y * 32 + threadIdx.x;
    bf16* Hi = (WHICH == 0) ? g_wahi : g_wphi;
    bf16* Lo = (WHICH == 0) ? g_walo : g_wplo;
#pragma unroll
    for (int r = 0; r < 4; ++r) {
        int n = blockIdx.x * 32 + threadIdx.y + r * 8;
        float v = tile[threadIdx.x][threadIdx.y + r * 8];
        bf16 h, l; bf16split(v, h, l);
        Hi[(size_t)n * 1024 + k] = h;
        Lo[(size_t)n * 1024 + k] = l;
    }
}

// ======================= HMMA split-bf16 GEMM (fused 3-term) ===============
// C[M,N] = A@B^T, terms hi*hi + lo*hi + hi*lo fused per K-slice.
// Block 128x128, 4 warps (2x2), warp tile 64x64, BK=32 (64B rows),
// stage = {Ahi,Alo,Bhi,Blo} x 8KB = 32KB; 3-stage cp.async; 2 CTAs/SM.
#define GEMM_STAGE_BYTES 32768
#define GEMM_SMEM_BYTES  (3 * GEMM_STAGE_BYTES)
#define NKC 32

template<int MODE>   // 0 = qkv (scatter split q/k/v), 1 = proj (dense fp32 out)
__global__ void __launch_bounds__(128, 2) hmma_gemm(
    const float* __restrict__ bias, float* __restrict__ out)
{
    extern __shared__ __align__(16) uint8_t sm[];
    const int t  = threadIdx.x;
    const int w  = t >> 5, l = t & 31;
    const int m0 = blockIdx.y * 128;
    const int n0 = blockIdx.x * 128;
    const int wm = (w & 1) * 64;
    const int wn = (w >> 1) * 64;

    const bf16* Ahi = (MODE == 0) ? g_xhi : g_chi;
    const bf16* Alo = (MODE == 0) ? g_xlo : g_clo;
    const bf16* Bhi = (MODE == 0) ? g_wahi : g_wphi;
    const bf16* Blo = (MODE == 0) ? g_walo : g_wplo;

    float acc[4][8][4];
#pragma unroll
    for (int i = 0; i < 4; ++i)
#pragma unroll
        for (int j = 0; j < 8; ++j)
#pragma unroll
            for (int v = 0; v < 4; ++v) acc[i][j][v] = 0.f;

    auto stage_load = [&](int kc, int st) {
        const int koff = kc * 32;
        uint32_t base = smem_u32(sm) + st * GEMM_STAGE_BYTES;
#pragma unroll
        for (int i = 0; i < 4; ++i) {
            int idx = t + 128 * i;            // 0..511
            int row = idx >> 2, sg = idx & 3;
            uint32_t sw = row * 64 + ((sg ^ ((row >> 1) & 3)) << 4);
            size_t aoff = (size_t)(m0 + row) * 1024 + koff + sg * 8;
            size_t boff = (size_t)(n0 + row) * 1024 + koff + sg * 8;
            cp16(base +         sw, Ahi + aoff);
            cp16(base +  8192 + sw, Alo + aoff);
            cp16(base + 16384 + sw, Bhi + boff);
            cp16(base + 24576 + sw, Blo + boff);
        }
        CP_COMMIT();
    };

    stage_load(0, 0);
    stage_load(1, 1);

    for (int kc = 0; kc < NKC; ++kc) {
        if (kc == NKC - 1) { CP_WAIT0(); } else { CP_WAIT1(); }
        __syncthreads();
        if (kc + 2 < NKC) stage_load(kc + 2, (kc + 2) % 3);

        const uint32_t base = smem_u32(sm) + (kc % 3) * GEMM_STAGE_BYTES;
        const uint32_t bAh = base, bAl = base + 8192;
        const uint32_t bBh = base + 16384, bBl = base + 24576;

#pragma unroll
        for (int kt = 0; kt < 2; ++kt) {
            uint32_t aH[4][4], aL[4][4];
#pragma unroll
            for (int mi = 0; mi < 4; ++mi) {
                int r = wm + 16 * mi + (l & 15);
                int c = 2 * kt + (l >> 4);
                uint32_t off = r * 64 + ((c ^ ((r >> 1) & 3)) << 4);
                ldsm_x4(aH[mi], bAh + off);
                ldsm_x4(aL[mi], bAl + off);
            }
#pragma unroll
            for (int ni2 = 0; ni2 < 4; ++ni2) {
                int r = wn + 16 * ni2 + (l & 7) + ((l >> 4) & 1) * 8;
                int c = 2 * kt + ((l >> 3) & 1);
                uint32_t off = r * 64 + ((c ^ ((r >> 1) & 3)) << 4);
                uint32_t bH[4], bL[4];
                ldsm_x4(bH, bBh + off);
                ldsm_x4(bL, bBl + off);
#pragma unroll
                for (int mi = 0; mi < 4; ++mi) {
                    mma16816(acc[mi][2 * ni2],     aH[mi], bH[0], bH[1]);
                    mma16816(acc[mi][2 * ni2 + 1], aH[mi], bH[2], bH[3]);
                    mma16816(acc[mi][2 * ni2],     aL[mi], bH[0], bH[1]);
                    mma16816(acc[mi][2 * ni2 + 1], aL[mi], bH[2], bH[3]);
                    mma16816(acc[mi][2 * ni2],     aH[mi], bL[0], bL[1]);
                    mma16816(acc[mi][2 * ni2 + 1], aH[mi], bL[2], bL[3]);
                }
            }
        }
    }

    // ---------------- epilogue ----------------
    const int part = n0 >> 10;   // uniform per block (128 | 1024)
#pragma unroll
    for (int mi = 0; mi < 4; ++mi) {
#pragma unroll
        for (int ni = 0; ni < 8; ++ni) {
            int gr = m0 + wm + 16 * mi + (l >> 2);
            int gc = n0 + wn + 8 * ni + 2 * (l & 3);
            float b0 = bias[gc], b1 = bias[gc + 1];
#pragma unroll
            for (int h2 = 0; h2 < 2; ++h2) {
                int row = gr + 8 * h2;
                float v0 = acc[mi][ni][2 * h2]     + b0;
                float v1 = acc[mi][ni][2 * h2 + 1] + b1;
                if (MODE == 1) {
                    float2 o; o.x = v0; o.y = v1;
                    *(float2*)(out + (size_t)row * 1024 + gc) = o;
                } else {
                    int rem = gc & 1023;
                    int hh  = rem >> 6, dd = rem & 63;
                    int bb  = row >> 11, s = row & 2047;
                    size_t idx = (((size_t)(bb * 16 + hh) * 2048) + s) * 64 + dd;
                    if (part == 0) { v0 *= 0.125f; v1 *= 0.125f; }
                    uint32_t H, L;
                    split_pack(v0, v1, H, L);
                    bf16* dHi = (part == 0) ? g_qhi : ((part == 1) ? g_khi : g_vhi);
                    bf16* dLo = (part == 0) ? g_qlo : ((part == 1) ? g_klo : g_vlo);
                    *(uint32_t*)(dHi + idx) = H;
                    *(uint32_t*)(dLo + idx) = L;
                }
            }
        }
    }
}

// ======================= HMMA flash attention ==============================
// Block: (q-tile 64, bh). 128 threads = 4 warps (2 CTAs/SM); warp w owns q rows
// 16w..16w+15. k-tile 64, double-buffered cp.async K/V. Split bf16 ctx out.
__global__ void __launch_bounds__(128) attn_hmma()
{
    // 2 stages x (Kh,Kl,Vh,Vl) x 8KB = 64KB
    __shared__ __align__(16) uint8_t sKV[2][4][8192];

    const int t  = threadIdx.x;
    const int w  = t >> 5, l = t & 31;
    const int qt = blockIdx.x;
    const int bh = blockIdx.y;
    const int q0 = qt * 64;

    const bf16* qh = g_qhi + (size_t)bh * S_LEN * HD;
    const bf16* ql = g_qlo + (size_t)bh * S_LEN * HD;
    const bf16* kh = g_khi + (size_t)bh * S_LEN * HD;
    const bf16* kl = g_klo + (size_t)bh * S_LEN * HD;
    const bf16* vh = g_vhi + (size_t)bh * S_LEN * HD;
    const bf16* vl = g_vlo + (size_t)bh * S_LEN * HD;

    // Q A-fragments (hi & lo) straight from gmem; live in regs
    uint32_t aQh[4][4], aQl[4][4];
    const int gr = q0 + w * 16 + (l >> 2);
#pragma unroll
    for (int t16 = 0; t16 < 4; ++t16) {
#pragma unroll
        for (int rg = 0; rg < 4; ++rg) {
            int row = gr + (rg & 1) * 8;
            int col = 16 * t16 + 2 * (l & 3) + (rg >> 1) * 8;
            aQh[t16][rg] = *(const uint32_t*)(qh + (size_t)row * HD + col);
            aQl[t16][rg] = *(const uint32_t*)(ql + (size_t)row * HD + col);
        }
    }

    float m_i[2] = {-1e30f, -1e30f};
    float l_i[2] = {0.f, 0.f};
    float o[8][4];
#pragma unroll
    for (int nf = 0; nf < 8; ++nf)
#pragma unroll
        for (int v = 0; v < 4; ++v) o[nf][v] = 0.f;

    auto load_tile = [&](int kt) {
        const int st = kt & 1;
        const int k0 = kt * 64;
#pragma unroll
        for (int i = 0; i < 4; ++i) {
            int idx = t + 128 * i;
            int row = idx >> 3, sg = idx & 7;
            uint32_t sw = row * 128 + ((sg ^ (row & 7)) << 4);
            size_t goff = (size_t)(k0 + row) * HD + sg * 8;
            cp16(smem_u32(sKV[st][0]) + sw, kh + goff);
            cp16(smem_u32(sKV[st][1]) + sw, kl + goff);
            cp16(smem_u32(sKV[st][2]) + sw, vh + goff);
            cp16(smem_u32(sKV[st][3]) + sw, vl + goff);
        }
        CP_COMMIT();
    };

    const int ktiles = qt + 1;
    load_tile(0);

    for (int kt = 0; kt < ktiles; ++kt) {
        const int k0 = kt * 64;
        if (kt + 1 < ktiles) { load_tile(kt + 1); CP_WAIT1(); }
        else                 { CP_WAIT0(); }
        __syncthreads();

        const int st = kt & 1;
        const uint32_t bKh = smem_u32(sKV[st][0]);
        const uint32_t bKl = smem_u32(sKV[st][1]);
        const uint32_t bVh = smem_u32(sKV[st][2]);
        const uint32_t bVl = smem_u32(sKV[st][3]);

        // warps whose rows are all below this k-tile skip compute
        if (k0 <= q0 + w * 16 + 15) {
            // ---- S = Q K^T (3-pass) ----
            float sc[8][4];
#pragma unroll
            for (int nf = 0; nf < 8; ++nf)
#pragma unroll
                for (int v = 0; v < 4; ++v) sc[nf][v] = 0.f;

#pragma unroll
            for (int t16 = 0; t16 < 4; ++t16) {
#pragma unroll
                for (int nfp = 0; nfp < 4; ++nfp) {
                    int r = 16 * nfp + (l & 7) + ((l >> 4) & 1) * 8;
                    int c = 2 * t16 + ((l >> 3) & 1);
                    uint32_t off = r * 128 + ((c ^ (r & 7)) << 4);
                    uint32_t kh4[4], kl4[4];
                    ldsm_x4(kh4, bKh + off);
                    ldsm_x4(kl4, bKl + off);
                    mma16816(sc[2 * nfp],     aQh[t16], kh4[0], kh4[1]);
                    mma16816(sc[2 * nfp],     aQh[t16], kl4[0], kl4[1]);
                    mma16816(sc[2 * nfp],     aQl[t16], kh4[0], kh4[1]);
                    mma16816(sc[2 * nfp + 1], aQh[t16], kh4[2], kh4[3]);
                    mma16816(sc[2 * nfp + 1], aQh[t16], kl4[2], kl4[3]);
                    mma16816(sc[2 * nfp + 1], aQl[t16], kh4[2], kh4[3]);
                }
            }

            // causal mask (only tiles overlapping this warp's diagonal)
            if (k0 + 63 > q0 + w * 16) {
#pragma unroll
                for (int nf = 0; nf < 8; ++nf)
#pragma unroll
                    for (int v = 0; v < 4; ++v) {
                        int kg = k0 + 8 * nf + 2 * (l & 3) + (v & 1);
                        int qg = gr + 8 * (v >> 1);
                        if (kg > qg) sc[nf][v] = -1e30f;
                    }
            }

            // ---- online softmax ----
#pragma unroll
            for (int h = 0; h < 2; ++h) {
                float mt = -1e30f;
#pragma unroll
                for (int nf = 0; nf < 8; ++nf) {
                    mt = fmaxf(mt, sc[nf][2 * h]);
                    mt = fmaxf(mt, sc[nf][2 * h + 1]);
                }
                mt = fmaxf(mt, __shfl_xor_sync(0xffffffffu, mt, 1));
                mt = fmaxf(mt, __shfl_xor_sync(0xffffffffu, mt, 2));
                float mnew = fmaxf(m_i[h], mt);
                float corr = __expf(m_i[h] - mnew);
                float psum = 0.f;
#pragma unroll
                for (int nf = 0; nf < 8; ++nf) {
                    float p0 = __expf(sc[nf][2 * h]     - mnew);
                    float p1 = __expf(sc[nf][2 * h + 1] - mnew);
                    sc[nf][2 * h] = p0; sc[nf][2 * h + 1] = p1;
                    psum += p0 + p1;
                }
                psum += __shfl_xor_sync(0xffffffffu, psum, 1);
                psum += __shfl_xor_sync(0xffffffffu, psum, 2);
                l_i[h] = l_i[h] * corr + psum;
                m_i[h] = mnew;
#pragma unroll
                for (int nf = 0; nf < 8; ++nf) {
                    o[nf][2 * h]     *= corr;
                    o[nf][2 * h + 1] *= corr;
                }
            }

            // ---- repack P as split A-frags ----
            uint32_t aPh[4][4], aPl[4][4];
#pragma unroll
            for (int t16 = 0; t16 < 4; ++t16) {
                split_pack(sc[2 * t16][0],     sc[2 * t16][1],     aPh[t16][0], aPl[t16][0]);
                split_pack(sc[2 * t16][2],     sc[2 * t16][3],     aPh[t16][1], aPl[t16][1]);
                split_pack(sc[2 * t16 + 1][0], sc[2 * t16 + 1][1], aPh[t16][2], aPl[t16][2]);
                split_pack(sc[2 * t16 + 1][2], sc[2 * t16 + 1][3], aPh[t16][3], aPl[t16][3]);
            }

            // ---- O += P V (3-pass, V transposed via ldmatrix.trans) ----
#pragma unroll
            for (int t16 = 0; t16 < 4; ++t16) {
#pragma unroll
                for (int nfp = 0; nfp < 4; ++nfp) {
                    int r = 16 * t16 + (l & 7) + ((l >> 3) & 1) * 8;
                    int c = 2 * nfp + ((l >> 4) & 1);
                    uint32_t off = r * 128 + ((c ^ (r & 7)) << 4);
                    uint32_t vh4[4], vl4[4];
                    ldsm_x4_t(vh4, bVh + off);
                    ldsm_x4_t(vl4, bVl + off);
                    mma16816(o[2 * nfp],     aPh[t16], vh4[0], vh4[1]);
                    mma16816(o[2 * nfp],     aPh[t16], vl4[0], vl4[1]);
                    mma16816(o[2 * nfp],     aPl[t16], vh4[0], vh4[1]);
                    mma16816(o[2 * nfp + 1], aPh[t16], vh4[2], vh4[3]);
                    mma16816(o[2 * nfp + 1], aPh[t16], vl4[2], vl4[3]);
                    mma16816(o[2 * nfp + 1], aPl[t16], vh4[2], vh4[3]);
                }
            }
        }
        __syncthreads();   // stage reads done before it is overwritten
    }

    // ---- epilogue: normalize, split, write ctx as bf16 hi/lo ----
    const int bb = bh >> 4, hh = bh & 15;
#pragma unroll
    for (int h = 0; h < 2; ++h) {
        float inv = 1.f / l_i[h];
        int row = gr + 8 * h;
#pragma unroll
        for (int nf = 0; nf < 8; ++nf) {
            int d = 8 * nf + 2 * (l & 3);
            size_t idx = ((size_t)(bb * S_LEN + row)) * D_MODEL + hh * HD + d;
            uint32_t H, L;
            split_pack(o[nf][2 * h] * inv, o[nf][2 * h + 1] * inv, H, L);
            *(uint32_t*)(g_chi + idx) = H;
            *(uint32_t*)(g_clo + idx) = L;
        }
    }
}

// ===========================================================================
extern "C" void kernel_launch(void* const* d_in, const int* in_sizes, int n_in,
                              void* d_out, int out_size)
{
    const float* X  = (const float*)d_in[0];   // hidden_states [2,2048,1024]
    const float* Wa = (const float*)d_in[1];   // w_attn [1024,3072]
    const float* ba = (const float*)d_in[2];   // b_attn [3072]
    const float* Wp = (const float*)d_in[3];   // w_proj [1024,1024]
    const float* bp = (const float*)d_in[4];   // b_proj [1024]
    float* out = (float*)d_out;                // [2,2048,1024]

    cudaFuncSetAttribute(hmma_gemm<0>,
                         cudaFuncAttributeMaxDynamicSharedMemorySize, GEMM_SMEM_BYTES);
    cudaFuncSetAttribute(hmma_gemm<1>,
                         cudaFuncAttributeMaxDynamicSharedMemorySize, GEMM_SMEM_BYTES);

    conv_x_split<<<(M_TOT * D_MODEL / 4) / 256, 256>>>(X);
    conv_w_tsplit<0><<<dim3(96, 32), dim3(32, 8)>>>(Wa, 3072);
    conv_w_tsplit<1><<<dim3(32, 32), dim3(32, 8)>>>(Wp, 1024);

    hmma_gemm<0><<<dim3(24, 32), 128, GEMM_SMEM_BYTES>>>(ba, out);
    attn_hmma<<<dim3(32, 32), 128>>>();
    hmma_gemm<1><<<dim3(8, 32), 128, GEMM_SMEM_BYTES>>>(bp, out);
}

// round 9
// speedup vs baseline: 1.3890x; 1.2664x over previous
#include <cuda_runtime.h>
#include <cuda_bf16.h>
#include <cuda_fp16.h>
#include <cstdint>

#define B_SZ    2
#define S_LEN   2048
#define D_MODEL 1024
#define N_HEADS 16
#define HD      64
#define M_TOT   (B_SZ * S_LEN)   // 4096

typedef __nv_bfloat16 bf16;

// ---------------- scratch (device globals; no allocation allowed) ----------
__device__ bf16 g_xhi[M_TOT * D_MODEL];               // hidden split
__device__ bf16 g_xlo[M_TOT * D_MODEL];
__device__ bf16 g_wahi[3 * D_MODEL * D_MODEL];        // w_attn^T split [3072][1024]
__device__ bf16 g_walo[3 * D_MODEL * D_MODEL];
__device__ bf16 g_wphi[D_MODEL * D_MODEL];            // w_proj^T split [1024][1024]
__device__ bf16 g_wplo[D_MODEL * D_MODEL];
__device__ bf16 g_chi[M_TOT * D_MODEL];               // ctx split (written by attn)
__device__ bf16 g_clo[M_TOT * D_MODEL];

// attention operands, fp16 single-precision-pass, layout [B,H,S,hd]
__device__ __half g_q16[B_SZ * N_HEADS * S_LEN * HD];   // pre-scaled by 0.125
__device__ __half g_k16[B_SZ * N_HEADS * S_LEN * HD];
__device__ __half g_v16[B_SZ * N_HEADS * S_LEN * HD];

// ======================= helpers ===========================================
__device__ __forceinline__ uint32_t smem_u32(const void* p) {
    uint32_t a;
    asm("{ .reg .u64 t; cvta.to.shared.u64 t, %1; cvt.u32.u64 %0, t; }" : "=r"(a) : "l"(p));
    return a;
}
__device__ __forceinline__ void ldsm_x4(uint32_t (&r)[4], uint32_t addr) {
    asm volatile("ldmatrix.sync.aligned.m8n8.x4.shared.b16 {%0,%1,%2,%3}, [%4];"
        : "=r"(r[0]), "=r"(r[1]), "=r"(r[2]), "=r"(r[3]) : "r"(addr));
}
__device__ __forceinline__ void ldsm_x4_t(uint32_t (&r)[4], uint32_t addr) {
    asm volatile("ldmatrix.sync.aligned.m8n8.x4.trans.shared.b16 {%0,%1,%2,%3}, [%4];"
        : "=r"(r[0]), "=r"(r[1]), "=r"(r[2]), "=r"(r[3]) : "r"(addr));
}
__device__ __forceinline__ void mma16816(float (&c)[4], const uint32_t (&a)[4],
                                         uint32_t b0, uint32_t b1) {
    asm volatile("mma.sync.aligned.m16n8k16.row.col.f32.bf16.bf16.f32 "
        "{%0,%1,%2,%3}, {%4,%5,%6,%7}, {%8,%9}, {%0,%1,%2,%3};"
        : "+f"(c[0]), "+f"(c[1]), "+f"(c[2]), "+f"(c[3])
        : "r"(a[0]), "r"(a[1]), "r"(a[2]), "r"(a[3]), "r"(b0), "r"(b1));
}
__device__ __forceinline__ void mma16816h(float (&c)[4], const uint32_t (&a)[4],
                                          uint32_t b0, uint32_t b1) {
    asm volatile("mma.sync.aligned.m16n8k16.row.col.f32.f16.f16.f32 "
        "{%0,%1,%2,%3}, {%4,%5,%6,%7}, {%8,%9}, {%0,%1,%2,%3};"
        : "+f"(c[0]), "+f"(c[1]), "+f"(c[2]), "+f"(c[3])
        : "r"(a[0]), "r"(a[1]), "r"(a[2]), "r"(a[3]), "r"(b0), "r"(b1));
}
__device__ __forceinline__ void cp16(uint32_t dst, const void* src) {
    asm volatile("cp.async.cg.shared.global [%0], [%1], 16;" :: "r"(dst), "l"(src));
}
#define CP_COMMIT() asm volatile("cp.async.commit_group;" ::: "memory")
#define CP_WAIT0()  asm volatile("cp.async.wait_group 0;" ::: "memory")
#define CP_WAIT1()  asm volatile("cp.async.wait_group 1;" ::: "memory")

// fast bf16 split: cvt.rn.bf16x2 + residual
__device__ __forceinline__ void split_pack(float p0, float p1, uint32_t& hi, uint32_t& lo) {
    uint32_t H;
    asm("cvt.rn.bf16x2.f32 %0, %1, %2;" : "=r"(H) : "f"(p1), "f"(p0));
    float h0 = __uint_as_float(H << 16);
    float h1 = __uint_as_float(H & 0xffff0000u);
    float l0 = p0 - h0, l1 = p1 - h1;
    uint32_t L;
    asm("cvt.rn.bf16x2.f32 %0, %1, %2;" : "=r"(L) : "f"(l1), "f"(l0));
    hi = H; lo = L;
}
__device__ __forceinline__ uint32_t pack_f16x2(float p0, float p1) {
    uint32_t r;
    asm("cvt.rn.f16x2.f32 %0, %1, %2;" : "=r"(r) : "f"(p1), "f"(p0));
    return r;
}
__device__ __forceinline__ void bf16split(float v, bf16& h, bf16& l) {
    h = __float2bfloat16_rn(v);
    l = __float2bfloat16_rn(v - __bfloat162float(h));
}

// ======================= conversion kernels ================================
__global__ void conv_x_split(const float* __restrict__ X) {
    int i = blockIdx.x * blockDim.x + threadIdx.x;     // float4 index
    float4 v = ((const float4*)X)[i];
    uint32_t h01, l01, h23, l23;
    split_pack(v.x, v.y, h01, l01);
    split_pack(v.z, v.w, h23, l23);
    ((uint32_t*)g_xhi)[i * 2]     = h01;
    ((uint32_t*)g_xhi)[i * 2 + 1] = h23;
    ((uint32_t*)g_xlo)[i * 2]     = l01;
    ((uint32_t*)g_xlo)[i * 2 + 1] = l23;
}

// transpose + split: W [K=1024][N] row-major  ->  Wt [N][1024]
template<int WHICH>  // 0: w_attn (N=3072), 1: w_proj (N=1024)
__global__ void conv_w_tsplit(const float* __restrict__ W, int N) {
    __shared__ float tile[32][33];
    int x = blockIdx.x * 32 + threadIdx.x;       // n
#pragma unroll
    for (int r = 0; r < 4; ++r) {
        int y = blockIdx.y * 32 + threadIdx.y + r * 8;   // k
        tile[threadIdx.y + r * 8][threadIdx.x] = W[(size_t)y * N + x];
    }
    __syncthreads();
    int k = blockIdx.y * 32 + threadIdx.x;
    bf16* Hi = (WHICH == 0) ? g_wahi : g_wphi;
    bf16* Lo = (WHICH == 0) ? g_walo : g_wplo;
#pragma unroll
    for (int r = 0; r < 4; ++r) {
        int n = blockIdx.x * 32 + threadIdx.y + r * 8;
        float v = tile[threadIdx.x][threadIdx.y + r * 8];
        bf16 h, l; bf16split(v, h, l);
        Hi[(size_t)n * 1024 + k] = h;
        Lo[(size_t)n * 1024 + k] = l;
    }
}

// ======================= HMMA split-bf16 GEMM (fused 3-term) ===============
// C[M,N] = A@B^T, terms hi*hi + lo*hi + hi*lo fused per K-slice.
// Block 128x128, 4 warps (2x2), warp tile 64x64, BK=32 (64B rows),
// stage = {Ahi,Alo,Bhi,Blo} x 8KB = 32KB; 3-stage cp.async; 2 CTAs/SM.
#define GEMM_STAGE_BYTES 32768
#define GEMM_SMEM_BYTES  (3 * GEMM_STAGE_BYTES)
#define NKC 32

template<int MODE>   // 0 = qkv (scatter fp16 q/k/v), 1 = proj (dense fp32 out)
__global__ void __launch_bounds__(128, 2) hmma_gemm(
    const float* __restrict__ bias, float* __restrict__ out)
{
    extern __shared__ __align__(16) uint8_t sm[];
    const int t  = threadIdx.x;
    const int w  = t >> 5, l = t & 31;
    const int m0 = blockIdx.y * 128;
    const int n0 = blockIdx.x * 128;
    const int wm = (w & 1) * 64;
    const int wn = (w >> 1) * 64;

    const bf16* Ahi = (MODE == 0) ? g_xhi : g_chi;
    const bf16* Alo = (MODE == 0) ? g_xlo : g_clo;
    const bf16* Bhi = (MODE == 0) ? g_wahi : g_wphi;
    const bf16* Blo = (MODE == 0) ? g_walo : g_wplo;

    float acc[4][8][4];
#pragma unroll
    for (int i = 0; i < 4; ++i)
#pragma unroll
        for (int j = 0; j < 8; ++j)
#pragma unroll
            for (int v = 0; v < 4; ++v) acc[i][j][v] = 0.f;

    auto stage_load = [&](int kc, int st) {
        const int koff = kc * 32;
        uint32_t base = smem_u32(sm) + st * GEMM_STAGE_BYTES;
#pragma unroll
        for (int i = 0; i < 4; ++i) {
            int idx = t + 128 * i;            // 0..511
            int row = idx >> 2, sg = idx & 3;
            uint32_t sw = row * 64 + ((sg ^ ((row >> 1) & 3)) << 4);
            size_t aoff = (size_t)(m0 + row) * 1024 + koff + sg * 8;
            size_t boff = (size_t)(n0 + row) * 1024 + koff + sg * 8;
            cp16(base +         sw, Ahi + aoff);
            cp16(base +  8192 + sw, Alo + aoff);
            cp16(base + 16384 + sw, Bhi + boff);
            cp16(base + 24576 + sw, Blo + boff);
        }
        CP_COMMIT();
    };

    stage_load(0, 0);
    stage_load(1, 1);

    for (int kc = 0; kc < NKC; ++kc) {
        if (kc == NKC - 1) { CP_WAIT0(); } else { CP_WAIT1(); }
        __syncthreads();
        if (kc + 2 < NKC) stage_load(kc + 2, (kc + 2) % 3);

        const uint32_t base = smem_u32(sm) + (kc % 3) * GEMM_STAGE_BYTES;
        const uint32_t bAh = base, bAl = base + 8192;
        const uint32_t bBh = base + 16384, bBl = base + 24576;

#pragma unroll
        for (int kt = 0; kt < 2; ++kt) {
            uint32_t aH[4][4], aL[4][4];
#pragma unroll
            for (int mi = 0; mi < 4; ++mi) {
                int r = wm + 16 * mi + (l & 15);
                int c = 2 * kt + (l >> 4);
                uint32_t off = r * 64 + ((c ^ ((r >> 1) & 3)) << 4);
                ldsm_x4(aH[mi], bAh + off);
                ldsm_x4(aL[mi], bAl + off);
            }
#pragma unroll
            for (int ni2 = 0; ni2 < 4; ++ni2) {
                int r = wn + 16 * ni2 + (l & 7) + ((l >> 4) & 1) * 8;
                int c = 2 * kt + ((l >> 3) & 1);
                uint32_t off = r * 64 + ((c ^ ((r >> 1) & 3)) << 4);
                uint32_t bH[4], bL[4];
                ldsm_x4(bH, bBh + off);
                ldsm_x4(bL, bBl + off);
#pragma unroll
                for (int mi = 0; mi < 4; ++mi) {
                    mma16816(acc[mi][2 * ni2],     aH[mi], bH[0], bH[1]);
                    mma16816(acc[mi][2 * ni2 + 1], aH[mi], bH[2], bH[3]);
                    mma16816(acc[mi][2 * ni2],     aL[mi], bH[0], bH[1]);
                    mma16816(acc[mi][2 * ni2 + 1], aL[mi], bH[2], bH[3]);
                    mma16816(acc[mi][2 * ni2],     aH[mi], bL[0], bL[1]);
                    mma16816(acc[mi][2 * ni2 + 1], aH[mi], bL[2], bL[3]);
                }
            }
        }
    }

    // ---------------- epilogue ----------------
    const int part = n0 >> 10;   // uniform per block (128 | 1024)
#pragma unroll
    for (int mi = 0; mi < 4; ++mi) {
#pragma unroll
        for (int ni = 0; ni < 8; ++ni) {
            int gr = m0 + wm + 16 * mi + (l >> 2);
            int gc = n0 + wn + 8 * ni + 2 * (l & 3);
            float b0 = bias[gc], b1 = bias[gc + 1];
#pragma unroll
            for (int h2 = 0; h2 < 2; ++h2) {
                int row = gr + 8 * h2;
                float v0 = acc[mi][ni][2 * h2]     + b0;
                float v1 = acc[mi][ni][2 * h2 + 1] + b1;
                if (MODE == 1) {
                    float2 o; o.x = v0; o.y = v1;
                    *(float2*)(out + (size_t)row * 1024 + gc) = o;
                } else {
                    int rem = gc & 1023;
                    int hh  = rem >> 6, dd = rem & 63;
                    int bb  = row >> 11, s = row & 2047;
                    size_t idx = (((size_t)(bb * 16 + hh) * 2048) + s) * 64 + dd;
                    if (part == 0) { v0 *= 0.125f; v1 *= 0.125f; }
                    __half* dst = (part == 0) ? g_q16 : ((part == 1) ? g_k16 : g_v16);
                    *(uint32_t*)(dst + idx) = pack_f16x2(v0, v1);
                }
            }
        }
    }
}

// ======================= HMMA flash attention (fp16 single-pass) ===========
// Block: (q-tile 64, bh). 128 threads = 4 warps (3 CTAs/SM); warp w owns q rows
// 16w..16w+15. k-tile 64, double-buffered cp.async K/V. Split bf16 ctx out.
__global__ void __launch_bounds__(128, 3) attn_hmma()
{
    // 2 stages x (K,V) x 8KB = 32KB
    __shared__ __align__(16) uint8_t sKV[2][2][8192];

    const int t  = threadIdx.x;
    const int w  = t >> 5, l = t & 31;
    const int qt = blockIdx.x;
    const int bh = blockIdx.y;
    const int q0 = qt * 64;

    const __half* qp = g_q16 + (size_t)bh * S_LEN * HD;
    const __half* kp = g_k16 + (size_t)bh * S_LEN * HD;
    const __half* vp = g_v16 + (size_t)bh * S_LEN * HD;

    // Q A-fragments straight from gmem; live in regs
    uint32_t aQ[4][4];
    const int gr = q0 + w * 16 + (l >> 2);
#pragma unroll
    for (int t16 = 0; t16 < 4; ++t16) {
#pragma unroll
        for (int rg = 0; rg < 4; ++rg) {
            int row = gr + (rg & 1) * 8;
            int col = 16 * t16 + 2 * (l & 3) + (rg >> 1) * 8;
            aQ[t16][rg] = *(const uint32_t*)(qp + (size_t)row * HD + col);
        }
    }

    float m_i[2] = {-1e30f, -1e30f};
    float l_i[2] = {0.f, 0.f};
    float o[8][4];
#pragma unroll
    for (int nf = 0; nf < 8; ++nf)
#pragma unroll
        for (int v = 0; v < 4; ++v) o[nf][v] = 0.f;

    auto load_tile = [&](int kt) {
        const int st = kt & 1;
        const int k0 = kt * 64;
#pragma unroll
        for (int i = 0; i < 4; ++i) {
            int idx = t + 128 * i;            // 0..511
            int row = idx >> 3, sg = idx & 7;
            uint32_t sw = row * 128 + ((sg ^ (row & 7)) << 4);
            size_t goff = (size_t)(k0 + row) * HD + sg * 8;
            cp16(smem_u32(sKV[st][0]) + sw, kp + goff);
            cp16(smem_u32(sKV[st][1]) + sw, vp + goff);
        }
        CP_COMMIT();
    };

    const int ktiles = qt + 1;
    load_tile(0);

    for (int kt = 0; kt < ktiles; ++kt) {
        const int k0 = kt * 64;
        if (kt + 1 < ktiles) { load_tile(kt + 1); CP_WAIT1(); }
        else                 { CP_WAIT0(); }
        __syncthreads();

        const int st = kt & 1;
        const uint32_t bK = smem_u32(sKV[st][0]);
        const uint32_t bV = smem_u32(sKV[st][1]);

        // ---- S = Q K^T ----
        float sc[8][4];
#pragma unroll
        for (int nf = 0; nf < 8; ++nf)
#pragma unroll
            for (int v = 0; v < 4; ++v) sc[nf][v] = 0.f;

#pragma unroll
        for (int t16 = 0; t16 < 4; ++t16) {
#pragma unroll
            for (int nfp = 0; nfp < 4; ++nfp) {
                int r = 16 * nfp + (l & 7) + ((l >> 4) & 1) * 8;
                int c = 2 * t16 + ((l >> 3) & 1);
                uint32_t off = r * 128 + ((c ^ (r & 7)) << 4);
                uint32_t k4[4];
                ldsm_x4(k4, bK + off);
                mma16816h(sc[2 * nfp],     aQ[t16], k4[0], k4[1]);
                mma16816h(sc[2 * nfp + 1], aQ[t16], k4[2], k4[3]);
            }
        }

        // causal mask (only the diagonal tile needs it)
        if (k0 + 63 > q0 + w * 16) {
#pragma unroll
            for (int nf = 0; nf < 8; ++nf)
#pragma unroll
                for (int v = 0; v < 4; ++v) {
                    int kg = k0 + 8 * nf + 2 * (l & 3) + (v & 1);
                    int qg = gr + 8 * (v >> 1);
                    if (kg > qg) sc[nf][v] = -1e30f;
                }
        }

        // ---- online softmax ----
#pragma unroll
        for (int h = 0; h < 2; ++h) {
            float mt = -1e30f;
#pragma unroll
            for (int nf = 0; nf < 8; ++nf) {
                mt = fmaxf(mt, sc[nf][2 * h]);
                mt = fmaxf(mt, sc[nf][2 * h + 1]);
            }
            mt = fmaxf(mt, __shfl_xor_sync(0xffffffffu, mt, 1));
            mt = fmaxf(mt, __shfl_xor_sync(0xffffffffu, mt, 2));
            float mnew = fmaxf(m_i[h], mt);
            float corr = __expf(m_i[h] - mnew);
            float psum = 0.f;
#pragma unroll
            for (int nf = 0; nf < 8; ++nf) {
                float p0 = __expf(sc[nf][2 * h]     - mnew);
                float p1 = __expf(sc[nf][2 * h + 1] - mnew);
                sc[nf][2 * h] = p0; sc[nf][2 * h + 1] = p1;
                psum += p0 + p1;
            }
            psum += __shfl_xor_sync(0xffffffffu, psum, 1);
            psum += __shfl_xor_sync(0xffffffffu, psum, 2);
            l_i[h] = l_i[h] * corr + psum;
            m_i[h] = mnew;
#pragma unroll
            for (int nf = 0; nf < 8; ++nf) {
                o[nf][2 * h]     *= corr;
                o[nf][2 * h + 1] *= corr;
            }
        }

        // ---- repack P as fp16 A-frags ----
        uint32_t aP[4][4];
#pragma unroll
        for (int t16 = 0; t16 < 4; ++t16) {
            aP[t16][0] = pack_f16x2(sc[2 * t16][0],     sc[2 * t16][1]);
            aP[t16][1] = pack_f16x2(sc[2 * t16][2],     sc[2 * t16][3]);
            aP[t16][2] = pack_f16x2(sc[2 * t16 + 1][0], sc[2 * t16 + 1][1]);
            aP[t16][3] = pack_f16x2(sc[2 * t16 + 1][2], sc[2 * t16 + 1][3]);
        }

        // ---- O += P V (V transposed via ldmatrix.trans) ----
#pragma unroll
        for (int t16 = 0; t16 < 4; ++t16) {
#pragma unroll
            for (int nfp = 0; nfp < 4; ++nfp) {
                int r = 16 * t16 + (l & 7) + ((l >> 3) & 1) * 8;
                int c = 2 * nfp + ((l >> 4) & 1);
                uint32_t off = r * 128 + ((c ^ (r & 7)) << 4);
                uint32_t v4[4];
                ldsm_x4_t(v4, bV + off);
                mma16816h(o[2 * nfp],     aP[t16], v4[0], v4[1]);
                mma16816h(o[2 * nfp + 1], aP[t16], v4[2], v4[3]);
            }
        }
        __syncthreads();   // stage reads done before it is overwritten
    }

    // ---- epilogue: normalize, split, write ctx as bf16 hi/lo ----
    const int bb = bh >> 4, hh = bh & 15;
#pragma unroll
    for (int h = 0; h < 2; ++h) {
        float inv = 1.f / l_i[h];
        int row = gr + 8 * h;
#pragma unroll
        for (int nf = 0; nf < 8; ++nf) {
            int d = 8 * nf + 2 * (l & 3);
            size_t idx = ((size_t)(bb * S_LEN + row)) * D_MODEL + hh * HD + d;
            uint32_t H, L;
            split_pack(o[nf][2 * h] * inv, o[nf][2 * h + 1] * inv, H, L);
            *(uint32_t*)(g_chi + idx) = H;
            *(uint32_t*)(g_clo + idx) = L;
        }
    }
}

// ===========================================================================
extern "C" void kernel_launch(void* const* d_in, const int* in_sizes, int n_in,
                              void* d_out, int out_size)
{
    const float* X  = (const float*)d_in[0];   // hidden_states [2,2048,1024]
    const float* Wa = (const float*)d_in[1];   // w_attn [1024,3072]
    const float* ba = (const float*)d_in[2];   // b_attn [3072]
    const float* Wp = (const float*)d_in[3];   // w_proj [1024,1024]
    const float* bp = (const float*)d_in[4];   // b_proj [1024]
    float* out = (float*)d_out;                // [2,2048,1024]

    cudaFuncSetAttribute(hmma_gemm<0>,
                         cudaFuncAttributeMaxDynamicSharedMemorySize, GEMM_SMEM_BYTES);
    cudaFuncSetAttribute(hmma_gemm<1>,
                         cudaFuncAttributeMaxDynamicSharedMemorySize, GEMM_SMEM_BYTES);

    conv_x_split<<<(M_TOT * D_MODEL / 4) / 256, 256>>>(X);
    conv_w_tsplit<0><<<dim3(96, 32), dim3(32, 8)>>>(Wa, 3072);
    conv_w_tsplit<1><<<dim3(32, 32), dim3(32, 8)>>>(Wp, 1024);

    hmma_gemm<0><<<dim3(24, 32), 128, GEMM_SMEM_BYTES>>>(ba, out);
    attn_hmma<<<dim3(32, 32), 128>>>();
    hmma_gemm<1><<<dim3(8, 32), 128, GEMM_SMEM_BYTES>>>(bp, out);
}

// round 10
// speedup vs baseline: 1.6638x; 1.1978x over previous
#include <cuda_runtime.h>
#include <cuda_bf16.h>
#include <cuda_fp16.h>
#include <cstdint>

#define B_SZ    2
#define S_LEN   2048
#define D_MODEL 1024
#define N_HEADS 16
#define HD      64
#define M_TOT   (B_SZ * S_LEN)   // 4096

// ---------------- scratch (device globals; no allocation allowed) ----------
__device__ __half g_xh16[M_TOT * D_MODEL];            // X fp16 hi
__device__ __half g_xl16[M_TOT * D_MODEL];            // X fp16 residual
__device__ __half g_wa16[3 * D_MODEL * D_MODEL];      // w_attn^T fp16 [3072][1024]
__device__ __half g_wp16[D_MODEL * D_MODEL];          // w_proj^T fp16 [1024][1024]
__device__ __half g_ch16[M_TOT * D_MODEL];            // ctx fp16 hi (from attn)
__device__ __half g_cl16[M_TOT * D_MODEL];            // ctx fp16 residual

// attention operands, fp16, layout [B,H,S,hd]
__device__ __half g_q16[B_SZ * N_HEADS * S_LEN * HD];   // pre-scaled by 0.125
__device__ __half g_k16[B_SZ * N_HEADS * S_LEN * HD];
__device__ __half g_v16[B_SZ * N_HEADS * S_LEN * HD];

// ======================= helpers ===========================================
__device__ __forceinline__ uint32_t smem_u32(const void* p) {
    uint32_t a;
    asm("{ .reg .u64 t; cvta.to.shared.u64 t, %1; cvt.u32.u64 %0, t; }" : "=r"(a) : "l"(p));
    return a;
}
__device__ __forceinline__ void ldsm_x4(uint32_t (&r)[4], uint32_t addr) {
    asm volatile("ldmatrix.sync.aligned.m8n8.x4.shared.b16 {%0,%1,%2,%3}, [%4];"
        : "=r"(r[0]), "=r"(r[1]), "=r"(r[2]), "=r"(r[3]) : "r"(addr));
}
__device__ __forceinline__ void ldsm_x4_t(uint32_t (&r)[4], uint32_t addr) {
    asm volatile("ldmatrix.sync.aligned.m8n8.x4.trans.shared.b16 {%0,%1,%2,%3}, [%4];"
        : "=r"(r[0]), "=r"(r[1]), "=r"(r[2]), "=r"(r[3]) : "r"(addr));
}
__device__ __forceinline__ void mma16816h(float (&c)[4], const uint32_t (&a)[4],
                                          uint32_t b0, uint32_t b1) {
    asm volatile("mma.sync.aligned.m16n8k16.row.col.f32.f16.f16.f32 "
        "{%0,%1,%2,%3}, {%4,%5,%6,%7}, {%8,%9}, {%0,%1,%2,%3};"
        : "+f"(c[0]), "+f"(c[1]), "+f"(c[2]), "+f"(c[3])
        : "r"(a[0]), "r"(a[1]), "r"(a[2]), "r"(a[3]), "r"(b0), "r"(b1));
}
__device__ __forceinline__ void cp16(uint32_t dst, const void* src) {
    asm volatile("cp.async.cg.shared.global [%0], [%1], 16;" :: "r"(dst), "l"(src));
}
#define CP_COMMIT() asm volatile("cp.async.commit_group;" ::: "memory")
#define CP_WAIT0()  asm volatile("cp.async.wait_group 0;" ::: "memory")
#define CP_WAIT1()  asm volatile("cp.async.wait_group 1;" ::: "memory")

__device__ __forceinline__ uint32_t pack_f16x2(float p0, float p1) {
    uint32_t r;
    asm("cvt.rn.f16x2.f32 %0, %1, %2;" : "=r"(r) : "f"(p1), "f"(p0));
    return r;
}
// fp16 2-way split: hi = rn(p), lo = rn(p - hi)
__device__ __forceinline__ void split_pack_h(float p0, float p1, uint32_t& hi, uint32_t& lo) {
    hi = pack_f16x2(p0, p1);
    __half2 h = *(__half2*)&hi;
    float h0 = __low2float(h), h1 = __high2float(h);
    lo = pack_f16x2(p0 - h0, p1 - h1);
}

// ======================= conversion kernels ================================
__global__ void conv_x_split(const float* __restrict__ X) {
    int i = blockIdx.x * blockDim.x + threadIdx.x;     // float4 index
    float4 v = ((const float4*)X)[i];
    uint32_t h01, l01, h23, l23;
    split_pack_h(v.x, v.y, h01, l01);
    split_pack_h(v.z, v.w, h23, l23);
    ((uint32_t*)g_xh16)[i * 2]     = h01;
    ((uint32_t*)g_xh16)[i * 2 + 1] = h23;
    ((uint32_t*)g_xl16)[i * 2]     = l01;
    ((uint32_t*)g_xl16)[i * 2 + 1] = l23;
}

// transpose + fp16 round: W [K=1024][N] row-major -> Wt [N][1024] fp16
template<int WHICH>  // 0: w_attn (N=3072), 1: w_proj (N=1024)
__global__ void conv_w_t(const float* __restrict__ W, int N) {
    __shared__ float tile[32][33];
    int x = blockIdx.x * 32 + threadIdx.x;       // n
#pragma unroll
    for (int r = 0; r < 4; ++r) {
        int y = blockIdx.y * 32 + threadIdx.y + r * 8;   // k
        tile[threadIdx.y + r * 8][threadIdx.x] = W[(size_t)y * N + x];
    }
    __syncthreads();
    int k = blockIdx.y * 32 + threadIdx.x;
    __half* Hi = (WHICH == 0) ? g_wa16 : g_wp16;
#pragma unroll
    for (int r = 0; r < 4; ++r) {
        int n = blockIdx.x * 32 + threadIdx.y + r * 8;
        Hi[(size_t)n * 1024 + k] = __float2half_rn(tile[threadIdx.x][threadIdx.y + r * 8]);
    }
}

// ======================= HMMA fp16 2-term GEMM =============================
// C[M,N] = (Ah+Al)@Bh^T  (B residual dropped; err ~2.8e-4 rel).
// Block 128x128, 4 warps (2x2), warp tile 64x64, BK=32 (64B rows),
// stage = {Ah,Al,Bh} x 8KB = 24KB; 3-stage cp.async; 2 CTAs/SM.
#define GEMM_STAGE_BYTES 24576
#define GEMM_SMEM_BYTES  (3 * GEMM_STAGE_BYTES)
#define NKC 32

template<int MODE>   // 0 = qkv (scatter fp16 q/k/v), 1 = proj (dense fp32 out)
__global__ void __launch_bounds__(128, 2) hmma_gemm(
    const float* __restrict__ bias, float* __restrict__ out)
{
    extern __shared__ __align__(16) uint8_t sm[];
    const int t  = threadIdx.x;
    const int w  = t >> 5, l = t & 31;
    const int m0 = blockIdx.y * 128;
    const int n0 = blockIdx.x * 128;
    const int wm = (w & 1) * 64;
    const int wn = (w >> 1) * 64;

    const __half* Ahi = (MODE == 0) ? g_xh16 : g_ch16;
    const __half* Alo = (MODE == 0) ? g_xl16 : g_cl16;
    const __half* Bhi = (MODE == 0) ? g_wa16 : g_wp16;

    float acc[4][8][4];
#pragma unroll
    for (int i = 0; i < 4; ++i)
#pragma unroll
        for (int j = 0; j < 8; ++j)
#pragma unroll
            for (int v = 0; v < 4; ++v) acc[i][j][v] = 0.f;

    auto stage_load = [&](int kc, int st) {
        const int koff = kc * 32;
        uint32_t base = smem_u32(sm) + st * GEMM_STAGE_BYTES;
#pragma unroll
        for (int i = 0; i < 4; ++i) {
            int idx = t + 128 * i;            // 0..511
            int row = idx >> 2, sg = idx & 3;
            uint32_t sw = row * 64 + ((sg ^ ((row >> 1) & 3)) << 4);
            size_t aoff = (size_t)(m0 + row) * 1024 + koff + sg * 8;
            size_t boff = (size_t)(n0 + row) * 1024 + koff + sg * 8;
            cp16(base +         sw, Ahi + aoff);
            cp16(base +  8192 + sw, Alo + aoff);
            cp16(base + 16384 + sw, Bhi + boff);
        }
        CP_COMMIT();
    };

    stage_load(0, 0);
    stage_load(1, 1);

    for (int kc = 0; kc < NKC; ++kc) {
        if (kc == NKC - 1) { CP_WAIT0(); } else { CP_WAIT1(); }
        __syncthreads();
        if (kc + 2 < NKC) stage_load(kc + 2, (kc + 2) % 3);

        const uint32_t base = smem_u32(sm) + (kc % 3) * GEMM_STAGE_BYTES;
        const uint32_t bAh = base, bAl = base + 8192;
        const uint32_t bBh = base + 16384;

#pragma unroll
        for (int kt = 0; kt < 2; ++kt) {
            uint32_t aH[4][4], aL[4][4];
#pragma unroll
            for (int mi = 0; mi < 4; ++mi) {
                int r = wm + 16 * mi + (l & 15);
                int c = 2 * kt + (l >> 4);
                uint32_t off = r * 64 + ((c ^ ((r >> 1) & 3)) << 4);
                ldsm_x4(aH[mi], bAh + off);
                ldsm_x4(aL[mi], bAl + off);
            }
#pragma unroll
            for (int ni2 = 0; ni2 < 4; ++ni2) {
                int r = wn + 16 * ni2 + (l & 7) + ((l >> 4) & 1) * 8;
                int c = 2 * kt + ((l >> 3) & 1);
                uint32_t off = r * 64 + ((c ^ ((r >> 1) & 3)) << 4);
                uint32_t bH[4];
                ldsm_x4(bH, bBh + off);
#pragma unroll
                for (int mi = 0; mi < 4; ++mi) {
                    mma16816h(acc[mi][2 * ni2],     aH[mi], bH[0], bH[1]);
                    mma16816h(acc[mi][2 * ni2 + 1], aH[mi], bH[2], bH[3]);
                    mma16816h(acc[mi][2 * ni2],     aL[mi], bH[0], bH[1]);
                    mma16816h(acc[mi][2 * ni2 + 1], aL[mi], bH[2], bH[3]);
                }
            }
        }
    }

    // ---------------- epilogue ----------------
    const int part = n0 >> 10;   // uniform per block (128 | 1024)
#pragma unroll
    for (int mi = 0; mi < 4; ++mi) {
#pragma unroll
        for (int ni = 0; ni < 8; ++ni) {
            int gr = m0 + wm + 16 * mi + (l >> 2);
            int gc = n0 + wn + 8 * ni + 2 * (l & 3);
            float b0 = bias[gc], b1 = bias[gc + 1];
#pragma unroll
            for (int h2 = 0; h2 < 2; ++h2) {
                int row = gr + 8 * h2;
                float v0 = acc[mi][ni][2 * h2]     + b0;
                float v1 = acc[mi][ni][2 * h2 + 1] + b1;
                if (MODE == 1) {
                    float2 o; o.x = v0; o.y = v1;
                    *(float2*)(out + (size_t)row * 1024 + gc) = o;
                } else {
                    int rem = gc & 1023;
                    int hh  = rem >> 6, dd = rem & 63;
                    int bb  = row >> 11, s = row & 2047;
                    size_t idx = (((size_t)(bb * 16 + hh) * 2048) + s) * 64 + dd;
                    if (part == 0) { v0 *= 0.125f; v1 *= 0.125f; }
                    __half* dst = (part == 0) ? g_q16 : ((part == 1) ? g_k16 : g_v16);
                    *(uint32_t*)(dst + idx) = pack_f16x2(v0, v1);
                }
            }
        }
    }
}

// ======================= HMMA flash attention (fp16 single-pass) ===========
// Block: (q-tile 64, bh). 128 threads = 4 warps (3 CTAs/SM); warp w owns q rows
// 16w..16w+15. k-tile 64, double-buffered cp.async K/V. fp16-split ctx out.
__global__ void __launch_bounds__(128, 3) attn_hmma()
{
    // 2 stages x (K,V) x 8KB = 32KB
    __shared__ __align__(16) uint8_t sKV[2][2][8192];

    const int t  = threadIdx.x;
    const int w  = t >> 5, l = t & 31;
    const int qt = blockIdx.x;
    const int bh = blockIdx.y;
    const int q0 = qt * 64;

    const __half* qp = g_q16 + (size_t)bh * S_LEN * HD;
    const __half* kp = g_k16 + (size_t)bh * S_LEN * HD;
    const __half* vp = g_v16 + (size_t)bh * S_LEN * HD;

    // Q A-fragments straight from gmem; live in regs
    uint32_t aQ[4][4];
    const int gr = q0 + w * 16 + (l >> 2);
#pragma unroll
    for (int t16 = 0; t16 < 4; ++t16) {
#pragma unroll
        for (int rg = 0; rg < 4; ++rg) {
            int row = gr + (rg & 1) * 8;
            int col = 16 * t16 + 2 * (l & 3) + (rg >> 1) * 8;
            aQ[t16][rg] = *(const uint32_t*)(qp + (size_t)row * HD + col);
        }
    }

    float m_i[2] = {-1e30f, -1e30f};
    float l_i[2] = {0.f, 0.f};
    float o[8][4];
#pragma unroll
    for (int nf = 0; nf < 8; ++nf)
#pragma unroll
        for (int v = 0; v < 4; ++v) o[nf][v] = 0.f;

    auto load_tile = [&](int kt) {
        const int st = kt & 1;
        const int k0 = kt * 64;
#pragma unroll
        for (int i = 0; i < 4; ++i) {
            int idx = t + 128 * i;            // 0..511
            int row = idx >> 3, sg = idx & 7;
            uint32_t sw = row * 128 + ((sg ^ (row & 7)) << 4);
            size_t goff = (size_t)(k0 + row) * HD + sg * 8;
            cp16(smem_u32(sKV[st][0]) + sw, kp + goff);
            cp16(smem_u32(sKV[st][1]) + sw, vp + goff);
        }
        CP_COMMIT();
    };

    const int ktiles = qt + 1;
    load_tile(0);

    for (int kt = 0; kt < ktiles; ++kt) {
        const int k0 = kt * 64;
        if (kt + 1 < ktiles) { load_tile(kt + 1); CP_WAIT1(); }
        else                 { CP_WAIT0(); }
        __syncthreads();

        const int st = kt & 1;
        const uint32_t bK = smem_u32(sKV[st][0]);
        const uint32_t bV = smem_u32(sKV[st][1]);

        // ---- S = Q K^T ----
        float sc[8][4];
#pragma unroll
        for (int nf = 0; nf < 8; ++nf)
#pragma unroll
            for (int v = 0; v < 4; ++v) sc[nf][v] = 0.f;

#pragma unroll
        for (int t16 = 0; t16 < 4; ++t16) {
#pragma unroll
            for (int nfp = 0; nfp < 4; ++nfp) {
                int r = 16 * nfp + (l & 7) + ((l >> 4) & 1) * 8;
                int c = 2 * t16 + ((l >> 3) & 1);
                uint32_t off = r * 128 + ((c ^ (r & 7)) << 4);
                uint32_t k4[4];
                ldsm_x4(k4, bK + off);
                mma16816h(sc[2 * nfp],     aQ[t16], k4[0], k4[1]);
                mma16816h(sc[2 * nfp + 1], aQ[t16], k4[2], k4[3]);
            }
        }

        // causal mask (only the diagonal tile needs it)
        if (k0 + 63 > q0 + w * 16) {
#pragma unroll
            for (int nf = 0; nf < 8; ++nf)
#pragma unroll
                for (int v = 0; v < 4; ++v) {
                    int kg = k0 + 8 * nf + 2 * (l & 3) + (v & 1);
                    int qg = gr + 8 * (v >> 1);
                    if (kg > qg) sc[nf][v] = -1e30f;
                }
        }

        // ---- online softmax ----
#pragma unroll
        for (int h = 0; h < 2; ++h) {
            float mt = -1e30f;
#pragma unroll
            for (int nf = 0; nf < 8; ++nf) {
                mt = fmaxf(mt, sc[nf][2 * h]);
                mt = fmaxf(mt, sc[nf][2 * h + 1]);
            }
            mt = fmaxf(mt, __shfl_xor_sync(0xffffffffu, mt, 1));
            mt = fmaxf(mt, __shfl_xor_sync(0xffffffffu, mt, 2));
            float mnew = fmaxf(m_i[h], mt);
            float corr = __expf(m_i[h] - mnew);
            float psum = 0.f;
#pragma unroll
            for (int nf = 0; nf < 8; ++nf) {
                float p0 = __expf(sc[nf][2 * h]     - mnew);
                float p1 = __expf(sc[nf][2 * h + 1] - mnew);
                sc[nf][2 * h] = p0; sc[nf][2 * h + 1] = p1;
                psum += p0 + p1;
            }
            psum += __shfl_xor_sync(0xffffffffu, psum, 1);
            psum += __shfl_xor_sync(0xffffffffu, psum, 2);
            l_i[h] = l_i[h] * corr + psum;
            m_i[h] = mnew;
#pragma unroll
            for (int nf = 0; nf < 8; ++nf) {
                o[nf][2 * h]     *= corr;
                o[nf][2 * h + 1] *= corr;
            }
        }

        // ---- repack P as fp16 A-frags ----
        uint32_t aP[4][4];
#pragma unroll
        for (int t16 = 0; t16 < 4; ++t16) {
            aP[t16][0] = pack_f16x2(sc[2 * t16][0],     sc[2 * t16][1]);
            aP[t16][1] = pack_f16x2(sc[2 * t16][2],     sc[2 * t16][3]);
            aP[t16][2] = pack_f16x2(sc[2 * t16 + 1][0], sc[2 * t16 + 1][1]);
            aP[t16][3] = pack_f16x2(sc[2 * t16 + 1][2], sc[2 * t16 + 1][3]);
        }

        // ---- O += P V (V transposed via ldmatrix.trans) ----
#pragma unroll
        for (int t16 = 0; t16 < 4; ++t16) {
#pragma unroll
            for (int nfp = 0; nfp < 4; ++nfp) {
                int r = 16 * t16 + (l & 7) + ((l >> 3) & 1) * 8;
                int c = 2 * nfp + ((l >> 4) & 1);
                uint32_t off = r * 128 + ((c ^ (r & 7)) << 4);
                uint32_t v4[4];
                ldsm_x4_t(v4, bV + off);
                mma16816h(o[2 * nfp],     aP[t16], v4[0], v4[1]);
                mma16816h(o[2 * nfp + 1], aP[t16], v4[2], v4[3]);
            }
        }
        __syncthreads();   // stage reads done before it is overwritten
    }

    // ---- epilogue: normalize, fp16-split, write ctx ----
    const int bb = bh >> 4, hh = bh & 15;
#pragma unroll
    for (int h = 0; h < 2; ++h) {
        float inv = 1.f / l_i[h];
        int row = gr + 8 * h;
#pragma unroll
        for (int nf = 0; nf < 8; ++nf) {
            int d = 8 * nf + 2 * (l & 3);
            size_t idx = ((size_t)(bb * S_LEN + row)) * D_MODEL + hh * HD + d;
            uint32_t H, L;
            split_pack_h(o[nf][2 * h] * inv, o[nf][2 * h + 1] * inv, H, L);
            *(uint32_t*)(g_ch16 + idx) = H;
            *(uint32_t*)(g_cl16 + idx) = L;
        }
    }
}

// ===========================================================================
extern "C" void kernel_launch(void* const* d_in, const int* in_sizes, int n_in,
                              void* d_out, int out_size)
{
    const float* X  = (const float*)d_in[0];   // hidden_states [2,2048,1024]
    const float* Wa = (const float*)d_in[1];   // w_attn [1024,3072]
    const float* ba = (const float*)d_in[2];   // b_attn [3072]
    const float* Wp = (const float*)d_in[3];   // w_proj [1024,1024]
    const float* bp = (const float*)d_in[4];   // b_proj [1024]
    float* out = (float*)d_out;                // [2,2048,1024]

    cudaFuncSetAttribute(hmma_gemm<0>,
                         cudaFuncAttributeMaxDynamicSharedMemorySize, GEMM_SMEM_BYTES);
    cudaFuncSetAttribute(hmma_gemm<1>,
                         cudaFuncAttributeMaxDynamicSharedMemorySize, GEMM_SMEM_BYTES);

    conv_x_split<<<(M_TOT * D_MODEL / 4) / 256, 256>>>(X);
    conv_w_t<0><<<dim3(96, 32), dim3(32, 8)>>>(Wa, 3072);
    conv_w_t<1><<<dim3(32, 32), dim3(32, 8)>>>(Wp, 1024);

    hmma_gemm<0><<<dim3(24, 32), 128, GEMM_SMEM_BYTES>>>(ba, out);
    attn_hmma<<<dim3(32, 32), 128>>>();
    hmma_gemm<1><<<dim3(8, 32), 128, GEMM_SMEM_BYTES>>>(bp, out);
}

// round 11
// speedup vs baseline: 2.4906x; 1.4970x over previous
#include <cuda_runtime.h>
#include <cuda_bf16.h>
#include <cuda_fp16.h>
#include <cstdint>

#define B_SZ    2
#define S_LEN   2048
#define D_MODEL 1024
#define N_HEADS 16
#define HD      64
#define M_TOT   (B_SZ * S_LEN)   // 4096

// ---------------- scratch (device globals; no allocation allowed) ----------
__device__ __half g_x16[M_TOT * D_MODEL];             // X fp16
__device__ __half g_wa16[3 * D_MODEL * D_MODEL];      // w_attn^T fp16 [3072][1024]
__device__ __half g_wp16[D_MODEL * D_MODEL];          // w_proj^T fp16 [1024][1024]
__device__ __half g_c16[M_TOT * D_MODEL];             // ctx fp16 (from attn)

// attention operands, fp16, layout [B,H,S,hd]
__device__ __half g_q16[B_SZ * N_HEADS * S_LEN * HD];   // pre-scaled by 0.125
__device__ __half g_k16[B_SZ * N_HEADS * S_LEN * HD];
__device__ __half g_v16[B_SZ * N_HEADS * S_LEN * HD];

// ======================= helpers ===========================================
__device__ __forceinline__ uint32_t smem_u32(const void* p) {
    uint32_t a;
    asm("{ .reg .u64 t; cvta.to.shared.u64 t, %1; cvt.u32.u64 %0, t; }" : "=r"(a) : "l"(p));
    return a;
}
__device__ __forceinline__ void ldsm_x4(uint32_t (&r)[4], uint32_t addr) {
    asm volatile("ldmatrix.sync.aligned.m8n8.x4.shared.b16 {%0,%1,%2,%3}, [%4];"
        : "=r"(r[0]), "=r"(r[1]), "=r"(r[2]), "=r"(r[3]) : "r"(addr));
}
__device__ __forceinline__ void ldsm_x4_t(uint32_t (&r)[4], uint32_t addr) {
    asm volatile("ldmatrix.sync.aligned.m8n8.x4.trans.shared.b16 {%0,%1,%2,%3}, [%4];"
        : "=r"(r[0]), "=r"(r[1]), "=r"(r[2]), "=r"(r[3]) : "r"(addr));
}
__device__ __forceinline__ void mma16816h(float (&c)[4], const uint32_t (&a)[4],
                                          uint32_t b0, uint32_t b1) {
    asm volatile("mma.sync.aligned.m16n8k16.row.col.f32.f16.f16.f32 "
        "{%0,%1,%2,%3}, {%4,%5,%6,%7}, {%8,%9}, {%0,%1,%2,%3};"
        : "+f"(c[0]), "+f"(c[1]), "+f"(c[2]), "+f"(c[3])
        : "r"(a[0]), "r"(a[1]), "r"(a[2]), "r"(a[3]), "r"(b0), "r"(b1));
}
__device__ __forceinline__ void cp16(uint32_t dst, const void* src) {
    asm volatile("cp.async.cg.shared.global [%0], [%1], 16;" :: "r"(dst), "l"(src));
}
#define CP_COMMIT() asm volatile("cp.async.commit_group;" ::: "memory")
#define CP_WAIT0()  asm volatile("cp.async.wait_group 0;" ::: "memory")
#define CP_WAIT1()  asm volatile("cp.async.wait_group 1;" ::: "memory")

__device__ __forceinline__ uint32_t pack_f16x2(float p0, float p1) {
    uint32_t r;
    asm("cvt.rn.f16x2.f32 %0, %1, %2;" : "=r"(r) : "f"(p1), "f"(p0));
    return r;
}

// ======================= conversion kernels ================================
__global__ void conv_x(const float* __restrict__ X) {
    int i = blockIdx.x * blockDim.x + threadIdx.x;     // float4 index
    float4 v = ((const float4*)X)[i];
    ((uint32_t*)g_x16)[i * 2]     = pack_f16x2(v.x, v.y);
    ((uint32_t*)g_x16)[i * 2 + 1] = pack_f16x2(v.z, v.w);
}

// transpose + fp16 round: W [K=1024][N] row-major -> Wt [N][1024] fp16
template<int WHICH>  // 0: w_attn (N=3072), 1: w_proj (N=1024)
__global__ void conv_w_t(const float* __restrict__ W, int N) {
    __shared__ float tile[32][33];
    int x = blockIdx.x * 32 + threadIdx.x;       // n
#pragma unroll
    for (int r = 0; r < 4; ++r) {
        int y = blockIdx.y * 32 + threadIdx.y + r * 8;   // k
        tile[threadIdx.y + r * 8][threadIdx.x] = W[(size_t)y * N + x];
    }
    __syncthreads();
    int k = blockIdx.y * 32 + threadIdx.x;
    __half* Hi = (WHICH == 0) ? g_wa16 : g_wp16;
#pragma unroll
    for (int r = 0; r < 4; ++r) {
        int n = blockIdx.x * 32 + threadIdx.y + r * 8;
        Hi[(size_t)n * 1024 + k] = __float2half_rn(tile[threadIdx.x][threadIdx.y + r * 8]);
    }
}

// ======================= HMMA fp16 GEMM ====================================
// C[M,N] = A@B^T pure fp16 inputs, fp32 accum.
// Block 128x128, 4 warps (2x2), warp tile 64x64, BK=32 (64B rows),
// stage = {A,B} x 8KB = 16KB; 3-stage cp.async; 2 CTAs/SM.
#define GEMM_STAGE_BYTES 16384
#define GEMM_SMEM_BYTES  (3 * GEMM_STAGE_BYTES)
#define NKC 32

template<int MODE>   // 0 = qkv (scatter fp16 q/k/v), 1 = proj (dense fp32 out)
__global__ void __launch_bounds__(128, 2) hmma_gemm(
    const float* __restrict__ bias, float* __restrict__ out)
{
    extern __shared__ __align__(16) uint8_t sm[];
    const int t  = threadIdx.x;
    const int w  = t >> 5, l = t & 31;
    const int m0 = blockIdx.y * 128;
    const int n0 = blockIdx.x * 128;
    const int wm = (w & 1) * 64;
    const int wn = (w >> 1) * 64;

    const __half* A = (MODE == 0) ? g_x16 : g_c16;
    const __half* B = (MODE == 0) ? g_wa16 : g_wp16;

    float acc[4][8][4];
#pragma unroll
    for (int i = 0; i < 4; ++i)
#pragma unroll
        for (int j = 0; j < 8; ++j)
#pragma unroll
            for (int v = 0; v < 4; ++v) acc[i][j][v] = 0.f;

    auto stage_load = [&](int kc, int st) {
        const int koff = kc * 32;
        uint32_t base = smem_u32(sm) + st * GEMM_STAGE_BYTES;
#pragma unroll
        for (int i = 0; i < 4; ++i) {
            int idx = t + 128 * i;            // 0..511
            int row = idx >> 2, sg = idx & 3;
            uint32_t sw = row * 64 + ((sg ^ ((row >> 1) & 3)) << 4);
            cp16(base +        sw, A + (size_t)(m0 + row) * 1024 + koff + sg * 8);
            cp16(base + 8192 + sw, B + (size_t)(n0 + row) * 1024 + koff + sg * 8);
        }
        CP_COMMIT();
    };

    stage_load(0, 0);
    stage_load(1, 1);

    for (int kc = 0; kc < NKC; ++kc) {
        if (kc == NKC - 1) { CP_WAIT0(); } else { CP_WAIT1(); }
        __syncthreads();
        if (kc + 2 < NKC) stage_load(kc + 2, (kc + 2) % 3);

        const uint32_t base = smem_u32(sm) + (kc % 3) * GEMM_STAGE_BYTES;
        const uint32_t bA = base, bB = base + 8192;

#pragma unroll
        for (int kt = 0; kt < 2; ++kt) {
            uint32_t a4[4][4];
#pragma unroll
            for (int mi = 0; mi < 4; ++mi) {
                int r = wm + 16 * mi + (l & 15);
                int c = 2 * kt + (l >> 4);
                uint32_t off = r * 64 + ((c ^ ((r >> 1) & 3)) << 4);
                ldsm_x4(a4[mi], bA + off);
            }
#pragma unroll
            for (int ni2 = 0; ni2 < 4; ++ni2) {
                int r = wn + 16 * ni2 + (l & 7) + ((l >> 4) & 1) * 8;
                int c = 2 * kt + ((l >> 3) & 1);
                uint32_t off = r * 64 + ((c ^ ((r >> 1) & 3)) << 4);
                uint32_t b4[4];
                ldsm_x4(b4, bB + off);
#pragma unroll
                for (int mi = 0; mi < 4; ++mi) {
                    mma16816h(acc[mi][2 * ni2],     a4[mi], b4[0], b4[1]);
                    mma16816h(acc[mi][2 * ni2 + 1], a4[mi], b4[2], b4[3]);
                }
            }
        }
    }

    // ---------------- epilogue ----------------
    const int part = n0 >> 10;   // uniform per block (128 | 1024)
#pragma unroll
    for (int mi = 0; mi < 4; ++mi) {
#pragma unroll
        for (int ni = 0; ni < 8; ++ni) {
            int gr = m0 + wm + 16 * mi + (l >> 2);
            int gc = n0 + wn + 8 * ni + 2 * (l & 3);
            float b0 = bias[gc], b1 = bias[gc + 1];
#pragma unroll
            for (int h2 = 0; h2 < 2; ++h2) {
                int row = gr + 8 * h2;
                float v0 = acc[mi][ni][2 * h2]     + b0;
                float v1 = acc[mi][ni][2 * h2 + 1] + b1;
                if (MODE == 1) {
                    float2 o; o.x = v0; o.y = v1;
                    *(float2*)(out + (size_t)row * 1024 + gc) = o;
                } else {
                    int rem = gc & 1023;
                    int hh  = rem >> 6, dd = rem & 63;
                    int bb  = row >> 11, s = row & 2047;
                    size_t idx = (((size_t)(bb * 16 + hh) * 2048) + s) * 64 + dd;
                    if (part == 0) { v0 *= 0.125f; v1 *= 0.125f; }
                    __half* dst = (part == 0) ? g_q16 : ((part == 1) ? g_k16 : g_v16);
                    *(uint32_t*)(dst + idx) = pack_f16x2(v0, v1);
                }
            }
        }
    }
}

// ======================= HMMA flash attention (fp16 single-pass) ===========
// Block: (q-tile 64, bh). 128 threads = 4 warps (3 CTAs/SM); warp w owns q rows
// 16w..16w+15. k-tile 64, double-buffered cp.async K/V. fp16 ctx out.
__global__ void __launch_bounds__(128, 3) attn_hmma()
{
    // 2 stages x (K,V) x 8KB = 32KB
    __shared__ __align__(16) uint8_t sKV[2][2][8192];

    const int t  = threadIdx.x;
    const int w  = t >> 5, l = t & 31;
    const int qt = blockIdx.x;
    const int bh = blockIdx.y;
    const int q0 = qt * 64;

    const __half* qp = g_q16 + (size_t)bh * S_LEN * HD;
    const __half* kp = g_k16 + (size_t)bh * S_LEN * HD;
    const __half* vp = g_v16 + (size_t)bh * S_LEN * HD;

    // Q A-fragments straight from gmem; live in regs
    uint32_t aQ[4][4];
    const int gr = q0 + w * 16 + (l >> 2);
#pragma unroll
    for (int t16 = 0; t16 < 4; ++t16) {
#pragma unroll
        for (int rg = 0; rg < 4; ++rg) {
            int row = gr + (rg & 1) * 8;
            int col = 16 * t16 + 2 * (l & 3) + (rg >> 1) * 8;
            aQ[t16][rg] = *(const uint32_t*)(qp + (size_t)row * HD + col);
        }
    }

    float m_i[2] = {-1e30f, -1e30f};
    float l_i[2] = {0.f, 0.f};
    float o[8][4];
#pragma unroll
    for (int nf = 0; nf < 8; ++nf)
#pragma unroll
        for (int v = 0; v < 4; ++v) o[nf][v] = 0.f;

    auto load_tile = [&](int kt) {
        const int st = kt & 1;
        const int k0 = kt * 64;
#pragma unroll
        for (int i = 0; i < 4; ++i) {
            int idx = t + 128 * i;            // 0..511
            int row = idx >> 3, sg = idx & 7;
            uint32_t sw = row * 128 + ((sg ^ (row & 7)) << 4);
            size_t goff = (size_t)(k0 + row) * HD + sg * 8;
            cp16(smem_u32(sKV[st][0]) + sw, kp + goff);
            cp16(smem_u32(sKV[st][1]) + sw, vp + goff);
        }
        CP_COMMIT();
    };

    const int ktiles = qt + 1;
    load_tile(0);

    for (int kt = 0; kt < ktiles; ++kt) {
        const int k0 = kt * 64;
        if (kt + 1 < ktiles) { load_tile(kt + 1); CP_WAIT1(); }
        else                 { CP_WAIT0(); }
        __syncthreads();

        const int st = kt & 1;
        const uint32_t bK = smem_u32(sKV[st][0]);
        const uint32_t bV = smem_u32(sKV[st][1]);

        // ---- S = Q K^T ----
        float sc[8][4];
#pragma unroll
        for (int nf = 0; nf < 8; ++nf)
#pragma unroll
            for (int v = 0; v < 4; ++v) sc[nf][v] = 0.f;

#pragma unroll
        for (int t16 = 0; t16 < 4; ++t16) {
#pragma unroll
            for (int nfp = 0; nfp < 4; ++nfp) {
                int r = 16 * nfp + (l & 7) + ((l >> 4) & 1) * 8;
                int c = 2 * t16 + ((l >> 3) & 1);
                uint32_t off = r * 128 + ((c ^ (r & 7)) << 4);
                uint32_t k4[4];
                ldsm_x4(k4, bK + off);
                mma16816h(sc[2 * nfp],     aQ[t16], k4[0], k4[1]);
                mma16816h(sc[2 * nfp + 1], aQ[t16], k4[2], k4[3]);
            }
        }

        // causal mask (only the diagonal tile needs it)
        if (k0 + 63 > q0 + w * 16) {
#pragma unroll
            for (int nf = 0; nf < 8; ++nf)
#pragma unroll
                for (int v = 0; v < 4; ++v) {
                    int kg = k0 + 8 * nf + 2 * (l & 3) + (v & 1);
                    int qg = gr + 8 * (v >> 1);
                    if (kg > qg) sc[nf][v] = -1e30f;
                }
        }

        // ---- online softmax ----
#pragma unroll
        for (int h = 0; h < 2; ++h) {
            float mt = -1e30f;
#pragma unroll
            for (int nf = 0; nf < 8; ++nf) {
                mt = fmaxf(mt, sc[nf][2 * h]);
                mt = fmaxf(mt, sc[nf][2 * h + 1]);
            }
            mt = fmaxf(mt, __shfl_xor_sync(0xffffffffu, mt, 1));
            mt = fmaxf(mt, __shfl_xor_sync(0xffffffffu, mt, 2));
            float mnew = fmaxf(m_i[h], mt);
            float corr = __expf(m_i[h] - mnew);
            float psum = 0.f;
#pragma unroll
            for (int nf = 0; nf < 8; ++nf) {
                float p0 = __expf(sc[nf][2 * h]     - mnew);
                float p1 = __expf(sc[nf][2 * h + 1] - mnew);
                sc[nf][2 * h] = p0; sc[nf][2 * h + 1] = p1;
                psum += p0 + p1;
            }
            psum += __shfl_xor_sync(0xffffffffu, psum, 1);
            psum += __shfl_xor_sync(0xffffffffu, psum, 2);
            l_i[h] = l_i[h] * corr + psum;
            m_i[h] = mnew;
#pragma unroll
            for (int nf = 0; nf < 8; ++nf) {
                o[nf][2 * h]     *= corr;
                o[nf][2 * h + 1] *= corr;
            }
        }

        // ---- repack P as fp16 A-frags ----
        uint32_t aP[4][4];
#pragma unroll
        for (int t16 = 0; t16 < 4; ++t16) {
            aP[t16][0] = pack_f16x2(sc[2 * t16][0],     sc[2 * t16][1]);
            aP[t16][1] = pack_f16x2(sc[2 * t16][2],     sc[2 * t16][3]);
            aP[t16][2] = pack_f16x2(sc[2 * t16 + 1][0], sc[2 * t16 + 1][1]);
            aP[t16][3] = pack_f16x2(sc[2 * t16 + 1][2], sc[2 * t16 + 1][3]);
        }

        // ---- O += P V (V transposed via ldmatrix.trans) ----
#pragma unroll
        for (int t16 = 0; t16 < 4; ++t16) {
#pragma unroll
            for (int nfp = 0; nfp < 4; ++nfp) {
                int r = 16 * t16 + (l & 7) + ((l >> 3) & 1) * 8;
                int c = 2 * nfp + ((l >> 4) & 1);
                uint32_t off = r * 128 + ((c ^ (r & 7)) << 4);
                uint32_t v4[4];
                ldsm_x4_t(v4, bV + off);
                mma16816h(o[2 * nfp],     aP[t16], v4[0], v4[1]);
                mma16816h(o[2 * nfp + 1], aP[t16], v4[2], v4[3]);
            }
        }
        __syncthreads();   // stage reads done before it is overwritten
    }

    // ---- epilogue: normalize, write ctx fp16 ----
    const int bb = bh >> 4, hh = bh & 15;
#pragma unroll
    for (int h = 0; h < 2; ++h) {
        float inv = 1.f / l_i[h];
        int row = gr + 8 * h;
#pragma unroll
        for (int nf = 0; nf < 8; ++nf) {
            int d = 8 * nf + 2 * (l & 3);
            size_t idx = ((size_t)(bb * S_LEN + row)) * D_MODEL + hh * HD + d;
            *(uint32_t*)(g_c16 + idx) = pack_f16x2(o[nf][2 * h] * inv,
                                                   o[nf][2 * h + 1] * inv);
        }
    }
}

// ===========================================================================
extern "C" void kernel_launch(void* const* d_in, const int* in_sizes, int n_in,
                              void* d_out, int out_size)
{
    const float* X  = (const float*)d_in[0];   // hidden_states [2,2048,1024]
    const float* Wa = (const float*)d_in[1];   // w_attn [1024,3072]
    const float* ba = (const float*)d_in[2];   // b_attn [3072]
    const float* Wp = (const float*)d_in[3];   // w_proj [1024,1024]
    const float* bp = (const float*)d_in[4];   // b_proj [1024]
    float* out = (float*)d_out;                // [2,2048,1024]

    cudaFuncSetAttribute(hmma_gemm<0>,
                         cudaFuncAttributeMaxDynamicSharedMemorySize, GEMM_SMEM_BYTES);
    cudaFuncSetAttribute(hmma_gemm<1>,
                         cudaFuncAttributeMaxDynamicSharedMemorySize, GEMM_SMEM_BYTES);

    conv_x<<<(M_TOT * D_MODEL / 4) / 256, 256>>>(X);
    conv_w_t<0><<<dim3(96, 32), dim3(32, 8)>>>(Wa, 3072);
    conv_w_t<1><<<dim3(32, 32), dim3(32, 8)>>>(Wp, 1024);

    hmma_gemm<0><<<dim3(24, 32), 128, GEMM_SMEM_BYTES>>>(ba, out);
    attn_hmma<<<dim3(32, 32), 128>>>();
    hmma_gemm<1><<<dim3(8, 32), 128, GEMM_SMEM_BYTES>>>(bp, out);
}

// round 12
// speedup vs baseline: 2.4955x; 1.0020x over previous
#include <cuda_runtime.h>
#include <cuda_bf16.h>
#include <cuda_fp16.h>
#include <cstdint>

#define B_SZ    2
#define S_LEN   2048
#define D_MODEL 1024
#define N_HEADS 16
#define HD      64
#define M_TOT   (B_SZ * S_LEN)   // 4096

// ---------------- scratch (device globals; no allocation allowed) ----------
__device__ __half g_x16[M_TOT * D_MODEL];             // X fp16
__device__ __half g_wa16[3 * D_MODEL * D_MODEL];      // w_attn^T fp16 [3072][1024]
__device__ __half g_wp16[D_MODEL * D_MODEL];          // w_proj^T fp16 [1024][1024]
__device__ __half g_c16[M_TOT * D_MODEL];             // ctx fp16 (from attn)

// attention operands, fp16, layout [B,H,S,hd]
__device__ __half g_q16[B_SZ * N_HEADS * S_LEN * HD];   // pre-scaled by 0.125
__device__ __half g_k16[B_SZ * N_HEADS * S_LEN * HD];
__device__ __half g_v16[B_SZ * N_HEADS * S_LEN * HD];

// ======================= helpers ===========================================
__device__ __forceinline__ uint32_t smem_u32(const void* p) {
    uint32_t a;
    asm("{ .reg .u64 t; cvta.to.shared.u64 t, %1; cvt.u32.u64 %0, t; }" : "=r"(a) : "l"(p));
    return a;
}
__device__ __forceinline__ void ldsm_x4(uint32_t (&r)[4], uint32_t addr) {
    asm volatile("ldmatrix.sync.aligned.m8n8.x4.shared.b16 {%0,%1,%2,%3}, [%4];"
        : "=r"(r[0]), "=r"(r[1]), "=r"(r[2]), "=r"(r[3]) : "r"(addr));
}
__device__ __forceinline__ void ldsm_x4_t(uint32_t (&r)[4], uint32_t addr) {
    asm volatile("ldmatrix.sync.aligned.m8n8.x4.trans.shared.b16 {%0,%1,%2,%3}, [%4];"
        : "=r"(r[0]), "=r"(r[1]), "=r"(r[2]), "=r"(r[3]) : "r"(addr));
}
__device__ __forceinline__ void mma16816h(float (&c)[4], const uint32_t (&a)[4],
                                          uint32_t b0, uint32_t b1) {
    asm volatile("mma.sync.aligned.m16n8k16.row.col.f32.f16.f16.f32 "
        "{%0,%1,%2,%3}, {%4,%5,%6,%7}, {%8,%9}, {%0,%1,%2,%3};"
        : "+f"(c[0]), "+f"(c[1]), "+f"(c[2]), "+f"(c[3])
        : "r"(a[0]), "r"(a[1]), "r"(a[2]), "r"(a[3]), "r"(b0), "r"(b1));
}
__device__ __forceinline__ void cp16(uint32_t dst, const void* src) {
    asm volatile("cp.async.cg.shared.global [%0], [%1], 16;" :: "r"(dst), "l"(src));
}
#define CP_COMMIT() asm volatile("cp.async.commit_group;" ::: "memory")
#define CP_WAIT0()  asm volatile("cp.async.wait_group 0;" ::: "memory")
#define CP_WAIT1()  asm volatile("cp.async.wait_group 1;" ::: "memory")

__device__ __forceinline__ uint32_t pack_f16x2(float p0, float p1) {
    uint32_t r;
    asm("cvt.rn.f16x2.f32 %0, %1, %2;" : "=r"(r) : "f"(p1), "f"(p0));
    return r;
}

// ======================= conversion kernels ================================
__global__ void conv_x(const float* __restrict__ X) {
    int i = blockIdx.x * blockDim.x + threadIdx.x;     // float4 index
    float4 v = ((const float4*)X)[i];
    ((uint32_t*)g_x16)[i * 2]     = pack_f16x2(v.x, v.y);
    ((uint32_t*)g_x16)[i * 2 + 1] = pack_f16x2(v.z, v.w);
}

// transpose + fp16 round: W [K=1024][N] row-major -> Wt [N][1024] fp16
template<int WHICH>  // 0: w_attn (N=3072), 1: w_proj (N=1024)
__global__ void conv_w_t(const float* __restrict__ W, int N) {
    __shared__ float tile[32][33];
    int x = blockIdx.x * 32 + threadIdx.x;       // n
#pragma unroll
    for (int r = 0; r < 4; ++r) {
        int y = blockIdx.y * 32 + threadIdx.y + r * 8;   // k
        tile[threadIdx.y + r * 8][threadIdx.x] = W[(size_t)y * N + x];
    }
    __syncthreads();
    int k = blockIdx.y * 32 + threadIdx.x;
    __half* Hi = (WHICH == 0) ? g_wa16 : g_wp16;
#pragma unroll
    for (int r = 0; r < 4; ++r) {
        int n = blockIdx.x * 32 + threadIdx.y + r * 8;
        Hi[(size_t)n * 1024 + k] = __float2half_rn(tile[threadIdx.x][threadIdx.y + r * 8]);
    }
}

// ======================= HMMA fp16 GEMM (persistent tiles) =================
// C[M,N] = A@B^T pure fp16 inputs, fp32 accum.
// Block 128x128, 4 warps (2x2), warp tile 64x64, BK=32 (64B rows),
// stage = {A,B} x 8KB = 16KB; 3-stage cp.async; 2 CTAs/SM.
// MODE 0: persistent loop over 768 tiles (24 n x 32 m) on a 296-block grid.
#define GEMM_STAGE_BYTES 16384
#define GEMM_SMEM_BYTES  (3 * GEMM_STAGE_BYTES)
#define NKC 32
#define QKV_TILES_N 24
#define QKV_TILES   768

template<int MODE>   // 0 = qkv (scatter fp16 q/k/v), 1 = proj (dense fp32 out)
__global__ void __launch_bounds__(128, 2) hmma_gemm(
    const float* __restrict__ bias, float* __restrict__ out)
{
    extern __shared__ __align__(16) uint8_t sm[];
    const int t  = threadIdx.x;
    const int w  = t >> 5, l = t & 31;
    const int wm = (w & 1) * 64;
    const int wn = (w >> 1) * 64;

    const __half* A = (MODE == 0) ? g_x16 : g_c16;
    const __half* B = (MODE == 0) ? g_wa16 : g_wp16;

    const int tile0   = blockIdx.x;
    const int tileCnt = (MODE == 0) ? QKV_TILES : (int)gridDim.x;
    const int stride  = (int)gridDim.x;

    for (int tile = tile0; tile < tileCnt; tile += stride) {
        const int m0 = (MODE == 0) ? (tile / QKV_TILES_N) * 128 : (tile >> 3) * 128;
        const int n0 = (MODE == 0) ? (tile % QKV_TILES_N) * 128 : (tile & 7) * 128;

        __syncthreads();   // prior tile's smem readers done before stage reuse

        float acc[4][8][4];
#pragma unroll
        for (int i = 0; i < 4; ++i)
#pragma unroll
            for (int j = 0; j < 8; ++j)
#pragma unroll
                for (int v = 0; v < 4; ++v) acc[i][j][v] = 0.f;

        auto stage_load = [&](int kc, int st) {
            const int koff = kc * 32;
            uint32_t base = smem_u32(sm) + st * GEMM_STAGE_BYTES;
#pragma unroll
            for (int i = 0; i < 4; ++i) {
                int idx = t + 128 * i;            // 0..511
                int row = idx >> 2, sg = idx & 3;
                uint32_t sw = row * 64 + ((sg ^ ((row >> 1) & 3)) << 4);
                cp16(base +        sw, A + (size_t)(m0 + row) * 1024 + koff + sg * 8);
                cp16(base + 8192 + sw, B + (size_t)(n0 + row) * 1024 + koff + sg * 8);
            }
            CP_COMMIT();
        };

        stage_load(0, 0);
        stage_load(1, 1);

        for (int kc = 0; kc < NKC; ++kc) {
            if (kc == NKC - 1) { CP_WAIT0(); } else { CP_WAIT1(); }
            __syncthreads();
            if (kc + 2 < NKC) stage_load(kc + 2, (kc + 2) % 3);

            const uint32_t base = smem_u32(sm) + (kc % 3) * GEMM_STAGE_BYTES;
            const uint32_t bA = base, bB = base + 8192;

#pragma unroll
            for (int kt = 0; kt < 2; ++kt) {
                uint32_t a4[4][4];
#pragma unroll
                for (int mi = 0; mi < 4; ++mi) {
                    int r = wm + 16 * mi + (l & 15);
                    int c = 2 * kt + (l >> 4);
                    uint32_t off = r * 64 + ((c ^ ((r >> 1) & 3)) << 4);
                    ldsm_x4(a4[mi], bA + off);
                }
#pragma unroll
                for (int ni2 = 0; ni2 < 4; ++ni2) {
                    int r = wn + 16 * ni2 + (l & 7) + ((l >> 4) & 1) * 8;
                    int c = 2 * kt + ((l >> 3) & 1);
                    uint32_t off = r * 64 + ((c ^ ((r >> 1) & 3)) << 4);
                    uint32_t b4[4];
                    ldsm_x4(b4, bB + off);
#pragma unroll
                    for (int mi = 0; mi < 4; ++mi) {
                        mma16816h(acc[mi][2 * ni2],     a4[mi], b4[0], b4[1]);
                        mma16816h(acc[mi][2 * ni2 + 1], a4[mi], b4[2], b4[3]);
                    }
                }
            }
        }

        // ---------------- epilogue ----------------
        const int part = n0 >> 10;   // uniform per tile (128 | 1024)
#pragma unroll
        for (int mi = 0; mi < 4; ++mi) {
#pragma unroll
            for (int ni = 0; ni < 8; ++ni) {
                int gr = m0 + wm + 16 * mi + (l >> 2);
                int gc = n0 + wn + 8 * ni + 2 * (l & 3);
                float b0 = bias[gc], b1 = bias[gc + 1];
#pragma unroll
                for (int h2 = 0; h2 < 2; ++h2) {
                    int row = gr + 8 * h2;
                    float v0 = acc[mi][ni][2 * h2]     + b0;
                    float v1 = acc[mi][ni][2 * h2 + 1] + b1;
                    if (MODE == 1) {
                        float2 o; o.x = v0; o.y = v1;
                        *(float2*)(out + (size_t)row * 1024 + gc) = o;
                    } else {
                        int rem = gc & 1023;
                        int hh  = rem >> 6, dd = rem & 63;
                        int bb  = row >> 11, s = row & 2047;
                        size_t idx = (((size_t)(bb * 16 + hh) * 2048) + s) * 64 + dd;
                        if (part == 0) { v0 *= 0.125f; v1 *= 0.125f; }
                        __half* dst = (part == 0) ? g_q16 : ((part == 1) ? g_k16 : g_v16);
                        *(uint32_t*)(dst + idx) = pack_f16x2(v0, v1);
                    }
                }
            }
        }
    }
}

// ======================= HMMA flash attention (fp16 single-pass) ===========
// Block: (q-tile 64, bh). 128 threads = 4 warps (3 CTAs/SM); warp w owns q rows
// 16w..16w+15. k-tile 64, double-buffered cp.async K/V. fp16 ctx out.
// qt is REVERSED (deepest blocks launch first) for triangle load balance.
__global__ void __launch_bounds__(128, 3) attn_hmma()
{
    // 2 stages x (K,V) x 8KB = 32KB
    __shared__ __align__(16) uint8_t sKV[2][2][8192];

    const int t  = threadIdx.x;
    const int w  = t >> 5, l = t & 31;
    const int qt = (int)gridDim.x - 1 - (int)blockIdx.x;   // deepest first
    const int bh = blockIdx.y;
    const int q0 = qt * 64;

    const __half* qp = g_q16 + (size_t)bh * S_LEN * HD;
    const __half* kp = g_k16 + (size_t)bh * S_LEN * HD;
    const __half* vp = g_v16 + (size_t)bh * S_LEN * HD;

    // Q A-fragments straight from gmem; live in regs
    uint32_t aQ[4][4];
    const int gr = q0 + w * 16 + (l >> 2);
#pragma unroll
    for (int t16 = 0; t16 < 4; ++t16) {
#pragma unroll
        for (int rg = 0; rg < 4; ++rg) {
            int row = gr + (rg & 1) * 8;
            int col = 16 * t16 + 2 * (l & 3) + (rg >> 1) * 8;
            aQ[t16][rg] = *(const uint32_t*)(qp + (size_t)row * HD + col);
        }
    }

    float m_i[2] = {-1e30f, -1e30f};
    float l_i[2] = {0.f, 0.f};
    float o[8][4];
#pragma unroll
    for (int nf = 0; nf < 8; ++nf)
#pragma unroll
        for (int v = 0; v < 4; ++v) o[nf][v] = 0.f;

    auto load_tile = [&](int kt) {
        const int st = kt & 1;
        const int k0 = kt * 64;
#pragma unroll
        for (int i = 0; i < 4; ++i) {
            int idx = t + 128 * i;            // 0..511
            int row = idx >> 3, sg = idx & 7;
            uint32_t sw = row * 128 + ((sg ^ (row & 7)) << 4);
            size_t goff = (size_t)(k0 + row) * HD + sg * 8;
            cp16(smem_u32(sKV[st][0]) + sw, kp + goff);
            cp16(smem_u32(sKV[st][1]) + sw, vp + goff);
        }
        CP_COMMIT();
    };

    const int ktiles = qt + 1;
    load_tile(0);

    for (int kt = 0; kt < ktiles; ++kt) {
        const int k0 = kt * 64;
        if (kt + 1 < ktiles) { load_tile(kt + 1); CP_WAIT1(); }
        else                 { CP_WAIT0(); }
        __syncthreads();

        const int st = kt & 1;
        const uint32_t bK = smem_u32(sKV[st][0]);
        const uint32_t bV = smem_u32(sKV[st][1]);

        // ---- S = Q K^T ----
        float sc[8][4];
#pragma unroll
        for (int nf = 0; nf < 8; ++nf)
#pragma unroll
            for (int v = 0; v < 4; ++v) sc[nf][v] = 0.f;

#pragma unroll
        for (int t16 = 0; t16 < 4; ++t16) {
#pragma unroll
            for (int nfp = 0; nfp < 4; ++nfp) {
                int r = 16 * nfp + (l & 7) + ((l >> 4) & 1) * 8;
                int c = 2 * t16 + ((l >> 3) & 1);
                uint32_t off = r * 128 + ((c ^ (r & 7)) << 4);
                uint32_t k4[4];
                ldsm_x4(k4, bK + off);
                mma16816h(sc[2 * nfp],     aQ[t16], k4[0], k4[1]);
                mma16816h(sc[2 * nfp + 1], aQ[t16], k4[2], k4[3]);
            }
        }

        // causal mask (only the diagonal tile needs it)
        if (k0 + 63 > q0 + w * 16) {
#pragma unroll
            for (int nf = 0; nf < 8; ++nf)
#pragma unroll
                for (int v = 0; v < 4; ++v) {
                    int kg = k0 + 8 * nf + 2 * (l & 3) + (v & 1);
                    int qg = gr + 8 * (v >> 1);
                    if (kg > qg) sc[nf][v] = -1e30f;
                }
        }

        // ---- online softmax ----
#pragma unroll
        for (int h = 0; h < 2; ++h) {
            float mt = -1e30f;
#pragma unroll
            for (int nf = 0; nf < 8; ++nf) {
                mt = fmaxf(mt, sc[nf][2 * h]);
                mt = fmaxf(mt, sc[nf][2 * h + 1]);
            }
            mt = fmaxf(mt, __shfl_xor_sync(0xffffffffu, mt, 1));
            mt = fmaxf(mt, __shfl_xor_sync(0xffffffffu, mt, 2));
            float mnew = fmaxf(m_i[h], mt);
            float corr = __expf(m_i[h] - mnew);
            float psum = 0.f;
#pragma unroll
            for (int nf = 0; nf < 8; ++nf) {
                float p0 = __expf(sc[nf][2 * h]     - mnew);
                float p1 = __expf(sc[nf][2 * h + 1] - mnew);
                sc[nf][2 * h] = p0; sc[nf][2 * h + 1] = p1;
                psum += p0 + p1;
            }
            psum += __shfl_xor_sync(0xffffffffu, psum, 1);
            psum += __shfl_xor_sync(0xffffffffu, psum, 2);
            l_i[h] = l_i[h] * corr + psum;
            m_i[h] = mnew;
#pragma unroll
            for (int nf = 0; nf < 8; ++nf) {
                o[nf][2 * h]     *= corr;
                o[nf][2 * h + 1] *= corr;
            }
        }

        // ---- repack P as fp16 A-frags ----
        uint32_t aP[4][4];
#pragma unroll
        for (int t16 = 0; t16 < 4; ++t16) {
            aP[t16][0] = pack_f16x2(sc[2 * t16][0],     sc[2 * t16][1]);
            aP[t16][1] = pack_f16x2(sc[2 * t16][2],     sc[2 * t16][3]);
            aP[t16][2] = pack_f16x2(sc[2 * t16 + 1][0], sc[2 * t16 + 1][1]);
            aP[t16][3] = pack_f16x2(sc[2 * t16 + 1][2], sc[2 * t16 + 1][3]);
        }

        // ---- O += P V (V transposed via ldmatrix.trans) ----
#pragma unroll
        for (int t16 = 0; t16 < 4; ++t16) {
#pragma unroll
            for (int nfp = 0; nfp < 4; ++nfp) {
                int r = 16 * t16 + (l & 7) + ((l >> 3) & 1) * 8;
                int c = 2 * nfp + ((l >> 4) & 1);
                uint32_t off = r * 128 + ((c ^ (r & 7)) << 4);
                uint32_t v4[4];
                ldsm_x4_t(v4, bV + off);
                mma16816h(o[2 * nfp],     aP[t16], v4[0], v4[1]);
                mma16816h(o[2 * nfp + 1], aP[t16], v4[2], v4[3]);
            }
        }
        __syncthreads();   // stage reads done before it is overwritten
    }

    // ---- epilogue: normalize, write ctx fp16 ----
    const int bb = bh >> 4, hh = bh & 15;
#pragma unroll
    for (int h = 0; h < 2; ++h) {
        float inv = 1.f / l_i[h];
        int row = gr + 8 * h;
#pragma unroll
        for (int nf = 0; nf < 8; ++nf) {
            int d = 8 * nf + 2 * (l & 3);
            size_t idx = ((size_t)(bb * S_LEN + row)) * D_MODEL + hh * HD + d;
            *(uint32_t*)(g_c16 + idx) = pack_f16x2(o[nf][2 * h] * inv,
                                                   o[nf][2 * h + 1] * inv);
        }
    }
}

// ===========================================================================
extern "C" void kernel_launch(void* const* d_in, const int* in_sizes, int n_in,
                              void* d_out, int out_size)
{
    const float* X  = (const float*)d_in[0];   // hidden_states [2,2048,1024]
    const float* Wa = (const float*)d_in[1];   // w_attn [1024,3072]
    const float* ba = (const float*)d_in[2];   // b_attn [3072]
    const float* Wp = (const float*)d_in[3];   // w_proj [1024,1024]
    const float* bp = (const float*)d_in[4];   // b_proj [1024]
    float* out = (float*)d_out;                // [2,2048,1024]

    cudaFuncSetAttribute(hmma_gemm<0>,
                         cudaFuncAttributeMaxDynamicSharedMemorySize, GEMM_SMEM_BYTES);
    cudaFuncSetAttribute(hmma_gemm<1>,
                         cudaFuncAttributeMaxDynamicSharedMemorySize, GEMM_SMEM_BYTES);

    conv_x<<<(M_TOT * D_MODEL / 4) / 256, 256>>>(X);
    conv_w_t<0><<<dim3(96, 32), dim3(32, 8)>>>(Wa, 3072);
    conv_w_t<1><<<dim3(32, 32), dim3(32, 8)>>>(Wp, 1024);

    hmma_gemm<0><<<296, 128, GEMM_SMEM_BYTES>>>(ba, out);     // persistent 768 tiles
    attn_hmma<<<dim3(32, 32), 128>>>();
    hmma_gemm<1><<<256, 128, GEMM_SMEM_BYTES>>>(bp, out);     // 256 tiles, 1 wave
}

// round 13
// speedup vs baseline: 2.5049x; 1.0038x over previous
#include <cuda_runtime.h>
#include <cuda_bf16.h>
#include <cuda_fp16.h>
#include <cstdint>

#define B_SZ    2
#define S_LEN   2048
#define D_MODEL 1024
#define N_HEADS 16
#define HD      64
#define M_TOT   (B_SZ * S_LEN)   // 4096

// ---------------- scratch (device globals; no allocation allowed) ----------
__device__ __half g_x16[M_TOT * D_MODEL];             // X fp16
__device__ __half g_wa16[3 * D_MODEL * D_MODEL];      // w_attn^T fp16 [3072][1024]
__device__ __half g_wp16[D_MODEL * D_MODEL];          // w_proj^T fp16 [1024][1024]
__device__ __half g_c16[M_TOT * D_MODEL];             // ctx fp16 (from attn)

// attention operands, fp16, layout [B,H,S,hd]
__device__ __half g_q16[B_SZ * N_HEADS * S_LEN * HD];   // pre-scaled by 0.125
__device__ __half g_k16[B_SZ * N_HEADS * S_LEN * HD];
__device__ __half g_v16[B_SZ * N_HEADS * S_LEN * HD];

// ======================= helpers ===========================================
__device__ __forceinline__ uint32_t smem_u32(const void* p) {
    uint32_t a;
    asm("{ .reg .u64 t; cvta.to.shared.u64 t, %1; cvt.u32.u64 %0, t; }" : "=r"(a) : "l"(p));
    return a;
}
__device__ __forceinline__ void ldsm_x4(uint32_t (&r)[4], uint32_t addr) {
    asm volatile("ldmatrix.sync.aligned.m8n8.x4.shared.b16 {%0,%1,%2,%3}, [%4];"
        : "=r"(r[0]), "=r"(r[1]), "=r"(r[2]), "=r"(r[3]) : "r"(addr));
}
__device__ __forceinline__ void ldsm_x4_t(uint32_t (&r)[4], uint32_t addr) {
    asm volatile("ldmatrix.sync.aligned.m8n8.x4.trans.shared.b16 {%0,%1,%2,%3}, [%4];"
        : "=r"(r[0]), "=r"(r[1]), "=r"(r[2]), "=r"(r[3]) : "r"(addr));
}
__device__ __forceinline__ void mma16816h(float (&c)[4], const uint32_t (&a)[4],
                                          uint32_t b0, uint32_t b1) {
    asm volatile("mma.sync.aligned.m16n8k16.row.col.f32.f16.f16.f32 "
        "{%0,%1,%2,%3}, {%4,%5,%6,%7}, {%8,%9}, {%0,%1,%2,%3};"
        : "+f"(c[0]), "+f"(c[1]), "+f"(c[2]), "+f"(c[3])
        : "r"(a[0]), "r"(a[1]), "r"(a[2]), "r"(a[3]), "r"(b0), "r"(b1));
}
__device__ __forceinline__ void cp16(uint32_t dst, const void* src) {
    asm volatile("cp.async.cg.shared.global [%0], [%1], 16;" :: "r"(dst), "l"(src));
}
#define CP_COMMIT() asm volatile("cp.async.commit_group;" ::: "memory")
#define CP_WAIT0()  asm volatile("cp.async.wait_group 0;" ::: "memory")
#define CP_WAIT1()  asm volatile("cp.async.wait_group 1;" ::: "memory")

__device__ __forceinline__ uint32_t pack_f16x2(float p0, float p1) {
    uint32_t r;
    asm("cvt.rn.f16x2.f32 %0, %1, %2;" : "=r"(r) : "f"(p1), "f"(p0));
    return r;
}

// ======================= conversion kernels ================================
__global__ void conv_x(const float* __restrict__ X) {
    int i = blockIdx.x * blockDim.x + threadIdx.x;     // float4 index
    float4 v = ((const float4*)X)[i];
    ((uint32_t*)g_x16)[i * 2]     = pack_f16x2(v.x, v.y);
    ((uint32_t*)g_x16)[i * 2 + 1] = pack_f16x2(v.z, v.w);
}

// transpose + fp16 round: W [K=1024][N] row-major -> Wt [N][1024] fp16
template<int WHICH>  // 0: w_attn (N=3072), 1: w_proj (N=1024)
__global__ void conv_w_t(const float* __restrict__ W, int N) {
    __shared__ float tile[32][33];
    int x = blockIdx.x * 32 + threadIdx.x;       // n
#pragma unroll
    for (int r = 0; r < 4; ++r) {
        int y = blockIdx.y * 32 + threadIdx.y + r * 8;   // k
        tile[threadIdx.y + r * 8][threadIdx.x] = W[(size_t)y * N + x];
    }
    __syncthreads();
    int k = blockIdx.y * 32 + threadIdx.x;
    __half* Hi = (WHICH == 0) ? g_wa16 : g_wp16;
#pragma unroll
    for (int r = 0; r < 4; ++r) {
        int n = blockIdx.x * 32 + threadIdx.y + r * 8;
        Hi[(size_t)n * 1024 + k] = __float2half_rn(tile[threadIdx.x][threadIdx.y + r * 8]);
    }
}

// ======================= HMMA fp16 GEMM (persistent, BK=64) ================
// C[M,N] = A@B^T pure fp16 inputs, fp32 accum.
// Block 128x128, 4 warps (2x2), warp tile 64x64, BK=64 (128B SW128 rows),
// stage = {A,B} x 16KB = 32KB; 3-stage cp.async; 2 CTAs/SM; NKC=16.
#define GEMM_STAGE_BYTES 32768
#define GEMM_SMEM_BYTES  (3 * GEMM_STAGE_BYTES)
#define NKC 16
#define QKV_TILES_N 24
#define QKV_TILES   768

template<int MODE>   // 0 = qkv (scatter fp16 q/k/v), 1 = proj (dense fp32 out)
__global__ void __launch_bounds__(128, 2) hmma_gemm(
    const float* __restrict__ bias, float* __restrict__ out)
{
    extern __shared__ __align__(16) uint8_t sm[];
    const int t  = threadIdx.x;
    const int w  = t >> 5, l = t & 31;
    const int wm = (w & 1) * 64;
    const int wn = (w >> 1) * 64;

    const __half* A = (MODE == 0) ? g_x16 : g_c16;
    const __half* B = (MODE == 0) ? g_wa16 : g_wp16;

    const int tile0   = blockIdx.x;
    const int tileCnt = (MODE == 0) ? QKV_TILES : (int)gridDim.x;
    const int stride  = (int)gridDim.x;

    for (int tile = tile0; tile < tileCnt; tile += stride) {
        const int m0 = (MODE == 0) ? (tile / QKV_TILES_N) * 128 : (tile >> 3) * 128;
        const int n0 = (MODE == 0) ? (tile % QKV_TILES_N) * 128 : (tile & 7) * 128;

        __syncthreads();   // prior tile's smem readers done before stage reuse

        float acc[4][8][4];
#pragma unroll
        for (int i = 0; i < 4; ++i)
#pragma unroll
            for (int j = 0; j < 8; ++j)
#pragma unroll
                for (int v = 0; v < 4; ++v) acc[i][j][v] = 0.f;

        auto stage_load = [&](int kc, int st) {
            const int koff = kc * 64;
            uint32_t sA = smem_u32(sm) + st * GEMM_STAGE_BYTES;
            uint32_t sB = sA + 16384;
#pragma unroll
            for (int i = 0; i < 8; ++i) {
                int idx = t + 128 * i;            // 0..1023
                int row = idx >> 3, sg = idx & 7;
                uint32_t sw = row * 128 + ((sg ^ (row & 7)) << 4);
                cp16(sA + sw, A + (size_t)(m0 + row) * 1024 + koff + sg * 8);
            }
#pragma unroll
            for (int i = 0; i < 8; ++i) {
                int idx = t + 128 * i;
                int row = idx >> 3, sg = idx & 7;
                uint32_t sw = row * 128 + ((sg ^ (row & 7)) << 4);
                cp16(sB + sw, B + (size_t)(n0 + row) * 1024 + koff + sg * 8);
            }
            CP_COMMIT();
        };

        stage_load(0, 0);
        stage_load(1, 1);

        for (int kc = 0; kc < NKC; ++kc) {
            if (kc == NKC - 1) { CP_WAIT0(); } else { CP_WAIT1(); }
            __syncthreads();
            if (kc + 2 < NKC) stage_load(kc + 2, (kc + 2) % 3);

            const uint32_t base = smem_u32(sm) + (kc % 3) * GEMM_STAGE_BYTES;
            const uint32_t bA = base, bB = base + 16384;

#pragma unroll
            for (int kt = 0; kt < 4; ++kt) {
                uint32_t a4[4][4];
#pragma unroll
                for (int mi = 0; mi < 4; ++mi) {
                    int r = wm + 16 * mi + (l & 15);
                    int c = 2 * kt + (l >> 4);
                    uint32_t off = r * 128 + ((c ^ (r & 7)) << 4);
                    ldsm_x4(a4[mi], bA + off);
                }
#pragma unroll
                for (int ni2 = 0; ni2 < 4; ++ni2) {
                    int r = wn + 16 * ni2 + (l & 7) + ((l >> 4) & 1) * 8;
                    int c = 2 * kt + ((l >> 3) & 1);
                    uint32_t off = r * 128 + ((c ^ (r & 7)) << 4);
                    uint32_t b4[4];
                    ldsm_x4(b4, bB + off);
#pragma unroll
                    for (int mi = 0; mi < 4; ++mi) {
                        mma16816h(acc[mi][2 * ni2],     a4[mi], b4[0], b4[1]);
                        mma16816h(acc[mi][2 * ni2 + 1], a4[mi], b4[2], b4[3]);
                    }
                }
            }
        }

        // ---------------- epilogue ----------------
        const int part = n0 >> 10;   // uniform per tile (128 | 1024)
#pragma unroll
        for (int mi = 0; mi < 4; ++mi) {
#pragma unroll
            for (int ni = 0; ni < 8; ++ni) {
                int gr = m0 + wm + 16 * mi + (l >> 2);
                int gc = n0 + wn + 8 * ni + 2 * (l & 3);
                float b0 = bias[gc], b1 = bias[gc + 1];
#pragma unroll
                for (int h2 = 0; h2 < 2; ++h2) {
                    int row = gr + 8 * h2;
                    float v0 = acc[mi][ni][2 * h2]     + b0;
                    float v1 = acc[mi][ni][2 * h2 + 1] + b1;
                    if (MODE == 1) {
                        float2 o; o.x = v0; o.y = v1;
                        *(float2*)(out + (size_t)row * 1024 + gc) = o;
                    } else {
                        int rem = gc & 1023;
                        int hh  = rem >> 6, dd = rem & 63;
                        int bb  = row >> 11, s = row & 2047;
                        size_t idx = (((size_t)(bb * 16 + hh) * 2048) + s) * 64 + dd;
                        if (part == 0) { v0 *= 0.125f; v1 *= 0.125f; }
                        __half* dst = (part == 0) ? g_q16 : ((part == 1) ? g_k16 : g_v16);
                        *(uint32_t*)(dst + idx) = pack_f16x2(v0, v1);
                    }
                }
            }
        }
    }
}

// ======================= HMMA flash attention (fp16 single-pass) ===========
// Block: (q-tile 64, bh). 128 threads = 4 warps (3 CTAs/SM); warp w owns q rows
// 16w..16w+15. k-tile 64, double-buffered cp.async K/V. fp16 ctx out.
__global__ void __launch_bounds__(128, 3) attn_hmma()
{
    // 2 stages x (K,V) x 8KB = 32KB
    __shared__ __align__(16) uint8_t sKV[2][2][8192];

    const int t  = threadIdx.x;
    const int w  = t >> 5, l = t & 31;
    const int qt = (int)gridDim.x - 1 - (int)blockIdx.x;   // deepest first
    const int bh = blockIdx.y;
    const int q0 = qt * 64;

    const __half* qp = g_q16 + (size_t)bh * S_LEN * HD;
    const __half* kp = g_k16 + (size_t)bh * S_LEN * HD;
    const __half* vp = g_v16 + (size_t)bh * S_LEN * HD;

    // Q A-fragments straight from gmem; live in regs
    uint32_t aQ[4][4];
    const int gr = q0 + w * 16 + (l >> 2);
#pragma unroll
    for (int t16 = 0; t16 < 4; ++t16) {
#pragma unroll
        for (int rg = 0; rg < 4; ++rg) {
            int row = gr + (rg & 1) * 8;
            int col = 16 * t16 + 2 * (l & 3) + (rg >> 1) * 8;
            aQ[t16][rg] = *(const uint32_t*)(qp + (size_t)row * HD + col);
        }
    }

    float m_i[2] = {-1e30f, -1e30f};
    float l_i[2] = {0.f, 0.f};
    float o[8][4];
#pragma unroll
    for (int nf = 0; nf < 8; ++nf)
#pragma unroll
        for (int v = 0; v < 4; ++v) o[nf][v] = 0.f;

    auto load_tile = [&](int kt) {
        const int st = kt & 1;
        const int k0 = kt * 64;
#pragma unroll
        for (int i = 0; i < 4; ++i) {
            int idx = t + 128 * i;            // 0..511
            int row = idx >> 3, sg = idx & 7;
            uint32_t sw = row * 128 + ((sg ^ (row & 7)) << 4);
            size_t goff = (size_t)(k0 + row) * HD + sg * 8;
            cp16(smem_u32(sKV[st][0]) + sw, kp + goff);
            cp16(smem_u32(sKV[st][1]) + sw, vp + goff);
        }
        CP_COMMIT();
    };

    const int ktiles = qt + 1;
    load_tile(0);

    for (int kt = 0; kt < ktiles; ++kt) {
        const int k0 = kt * 64;
        if (kt + 1 < ktiles) { load_tile(kt + 1); CP_WAIT1(); }
        else                 { CP_WAIT0(); }
        __syncthreads();

        const int st = kt & 1;
        const uint32_t bK = smem_u32(sKV[st][0]);
        const uint32_t bV = smem_u32(sKV[st][1]);

        // ---- S = Q K^T ----
        float sc[8][4];
#pragma unroll
        for (int nf = 0; nf < 8; ++nf)
#pragma unroll
            for (int v = 0; v < 4; ++v) sc[nf][v] = 0.f;

#pragma unroll
        for (int t16 = 0; t16 < 4; ++t16) {
#pragma unroll
            for (int nfp = 0; nfp < 4; ++nfp) {
                int r = 16 * nfp + (l & 7) + ((l >> 4) & 1) * 8;
                int c = 2 * t16 + ((l >> 3) & 1);
                uint32_t off = r * 128 + ((c ^ (r & 7)) << 4);
                uint32_t k4[4];
                ldsm_x4(k4, bK + off);
                mma16816h(sc[2 * nfp],     aQ[t16], k4[0], k4[1]);
                mma16816h(sc[2 * nfp + 1], aQ[t16], k4[2], k4[3]);
            }
        }

        // causal mask (only the diagonal tile needs it)
        if (k0 + 63 > q0 + w * 16) {
#pragma unroll
            for (int nf = 0; nf < 8; ++nf)
#pragma unroll
                for (int v = 0; v < 4; ++v) {
                    int kg = k0 + 8 * nf + 2 * (l & 3) + (v & 1);
                    int qg = gr + 8 * (v >> 1);
                    if (kg > qg) sc[nf][v] = -1e30f;
                }
        }

        // ---- online softmax ----
#pragma unroll
        for (int h = 0; h < 2; ++h) {
            float mt = -1e30f;
#pragma unroll
            for (int nf = 0; nf < 8; ++nf) {
                mt = fmaxf(mt, sc[nf][2 * h]);
                mt = fmaxf(mt, sc[nf][2 * h + 1]);
            }
            mt = fmaxf(mt, __shfl_xor_sync(0xffffffffu, mt, 1));
            mt = fmaxf(mt, __shfl_xor_sync(0xffffffffu, mt, 2));
            float mnew = fmaxf(m_i[h], mt);
            float corr = __expf(m_i[h] - mnew);
            float psum = 0.f;
#pragma unroll
            for (int nf = 0; nf < 8; ++nf) {
                float p0 = __expf(sc[nf][2 * h]     - mnew);
                float p1 = __expf(sc[nf][2 * h + 1] - mnew);
                sc[nf][2 * h] = p0; sc[nf][2 * h + 1] = p1;
                psum += p0 + p1;
            }
            psum += __shfl_xor_sync(0xffffffffu, psum, 1);
            psum += __shfl_xor_sync(0xffffffffu, psum, 2);
            l_i[h] = l_i[h] * corr + psum;
            m_i[h] = mnew;
#pragma unroll
            for (int nf = 0; nf < 8; ++nf) {
                o[nf][2 * h]     *= corr;
                o[nf][2 * h + 1] *= corr;
            }
        }

        // ---- repack P as fp16 A-frags ----
        uint32_t aP[4][4];
#pragma unroll
        for (int t16 = 0; t16 < 4; ++t16) {
            aP[t16][0] = pack_f16x2(sc[2 * t16][0],     sc[2 * t16][1]);
            aP[t16][1] = pack_f16x2(sc[2 * t16][2],     sc[2 * t16][3]);
            aP[t16][2] = pack_f16x2(sc[2 * t16 + 1][0], sc[2 * t16 + 1][1]);
            aP[t16][3] = pack_f16x2(sc[2 * t16 + 1][2], sc[2 * t16 + 1][3]);
        }

        // ---- O += P V (V transposed via ldmatrix.trans) ----
#pragma unroll
        for (int t16 = 0; t16 < 4; ++t16) {
#pragma unroll
            for (int nfp = 0; nfp < 4; ++nfp) {
                int r = 16 * t16 + (l & 7) + ((l >> 3) & 1) * 8;
                int c = 2 * nfp + ((l >> 4) & 1);
                uint32_t off = r * 128 + ((c ^ (r & 7)) << 4);
                uint32_t v4[4];
                ldsm_x4_t(v4, bV + off);
                mma16816h(o[2 * nfp],     aP[t16], v4[0], v4[1]);
                mma16816h(o[2 * nfp + 1], aP[t16], v4[2], v4[3]);
            }
        }
        __syncthreads();   // stage reads done before it is overwritten
    }

    // ---- epilogue: normalize, write ctx fp16 ----
    const int bb = bh >> 4, hh = bh & 15;
#pragma unroll
    for (int h = 0; h < 2; ++h) {
        float inv = 1.f / l_i[h];
        int row = gr + 8 * h;
#pragma unroll
        for (int nf = 0; nf < 8; ++nf) {
            int d = 8 * nf + 2 * (l & 3);
            size_t idx = ((size_t)(bb * S_LEN + row)) * D_MODEL + hh * HD + d;
            *(uint32_t*)(g_c16 + idx) = pack_f16x2(o[nf][2 * h] * inv,
                                                   o[nf][2 * h + 1] * inv);
        }
    }
}

// ===========================================================================
extern "C" void kernel_launch(void* const* d_in, const int* in_sizes, int n_in,
                              void* d_out, int out_size)
{
    const float* X  = (const float*)d_in[0];   // hidden_states [2,2048,1024]
    const float* Wa = (const float*)d_in[1];   // w_attn [1024,3072]
    const float* ba = (const float*)d_in[2];   // b_attn [3072]
    const float* Wp = (const float*)d_in[3];   // w_proj [1024,1024]
    const float* bp = (const float*)d_in[4];   // b_proj [1024]
    float* out = (float*)d_out;                // [2,2048,1024]

    cudaFuncSetAttribute(hmma_gemm<0>,
                         cudaFuncAttributeMaxDynamicSharedMemorySize, GEMM_SMEM_BYTES);
    cudaFuncSetAttribute(hmma_gemm<1>,
                         cudaFuncAttributeMaxDynamicSharedMemorySize, GEMM_SMEM_BYTES);

    conv_x<<<(M_TOT * D_MODEL / 4) / 256, 256>>>(X);
    conv_w_t<0><<<dim3(96, 32), dim3(32, 8)>>>(Wa, 3072);
    conv_w_t<1><<<dim3(32, 32), dim3(32, 8)>>>(Wp, 1024);

    hmma_gemm<0><<<296, 128, GEMM_SMEM_BYTES>>>(ba, out);     // persistent 768 tiles
    attn_hmma<<<dim3(32, 32), 128>>>();
    hmma_gemm<1><<<256, 128, GEMM_SMEM_BYTES>>>(bp, out);     // 256 tiles, 1 wave
}